// round 12
// baseline (speedup 1.0000x reference)
#include <cuda_runtime.h>
#include <cuda_bf16.h>
#include <math.h>
#include <stdint.h>

#define B_SZ 64
#define T_SZ 64
#define NI 2048
#define NH 2048
#define MBK 4
#define MN 128
#define MW 20
#define M_ROWS 4096
#define KW 4096   // compact split width [hi | lo]
#define KX 6144   // logical K (3 terms x 2048)
#define HNH 1024  // half hidden

// ---------------- device scratch (t-major rows: r = t*64 + b) ----------------
__device__ float g_pre[(size_t)M_ROWS * NH];
__device__ float g_bpre[NH];
__device__ __nv_bfloat16 g_Ax[(size_t)M_ROWS * KW];   // x split
__device__ __nv_bfloat16 g_Ah[(size_t)M_ROWS * KW];   // H split
__device__ __nv_bfloat16 g_B0[(size_t)NH * KW];       // W_in^T  [hi|lo]
__device__ __nv_bfloat16 g_B1[(size_t)NH * KW];       // W_out^T [hi|lo]
__device__ int g_kflag[128];                          // per half-block step flag
__device__ float g_kpart[128 * 2 * MW];               // DOUBLE-BUFFERED by t&1

// ---------------- helpers ----------------------------------------------------
__device__ __forceinline__ uint32_t s2u(const void* p) {
    uint32_t r;
    asm("{ .reg .u64 t; cvta.to.shared.u64 t, %1; cvt.u32.u64 %0, t; }"
        : "=r"(r) : "l"(p));
    return r;
}
#define SWZ(x) ((x) ^ (((x) >> 3) & 0x70))
__device__ __forceinline__ void cpa16(uint32_t s, const void* g) {
    asm volatile("cp.async.cg.shared.global [%0], [%1], 16;" :: "r"(s), "l"(g)
                 : "memory");
}
#define CP_COMMIT asm volatile("cp.async.commit_group;" ::: "memory")
__device__ __forceinline__ void cp_wait1() {
    asm volatile("cp.async.wait_group 1;" ::: "memory");
}
__device__ __forceinline__ void cp_wait0() {
    asm volatile("cp.async.wait_group 0;" ::: "memory");
}
__device__ __forceinline__ void ldsm4(uint32_t* r, uint32_t a) {
    asm volatile("ldmatrix.sync.aligned.m8n8.x4.shared.b16 {%0,%1,%2,%3}, [%4];"
                 : "=r"(r[0]), "=r"(r[1]), "=r"(r[2]), "=r"(r[3]) : "r"(a));
}
__device__ __forceinline__ void mma16816(float* c, const uint32_t* a,
                                         const uint32_t* b) {
    asm volatile(
        "mma.sync.aligned.m16n8k16.row.col.f32.bf16.bf16.f32 "
        "{%0,%1,%2,%3}, {%4,%5,%6,%7}, {%8,%9}, {%0,%1,%2,%3};"
        : "+f"(c[0]), "+f"(c[1]), "+f"(c[2]), "+f"(c[3])
        : "r"(a[0]), "r"(a[1]), "r"(a[2]), "r"(a[3]), "r"(b[0]), "r"(b[1]));
}

// ---------------- small prep kernels -----------------------------------------
__global__ void init_flags() {
    if (threadIdx.x < 128) g_kflag[threadIdx.x] = 0;
}

__global__ void conv_x(const float4* __restrict__ x4) {
    int i = blockIdx.x * 256 + threadIdx.x;
    if (i >= M_ROWS * NI / 4) return;
    int row = i >> 9, c4 = i & 511;          // input row = b*64 + t
    int b = row >> 6, t = row & 63;
    int orow = t * 64 + b;                   // t-major
    float4 v = x4[i];
    __nv_bfloat16 hx = __float2bfloat16(v.x), hy = __float2bfloat16(v.y);
    __nv_bfloat16 hz = __float2bfloat16(v.z), hw = __float2bfloat16(v.w);
    __nv_bfloat162* p = (__nv_bfloat162*)(g_Ax + (size_t)orow * KW);
    p[2 * c4] = __halves2bfloat162(hx, hy);
    p[2 * c4 + 1] = __halves2bfloat162(hz, hw);
    p[1024 + 2 * c4] = __halves2bfloat162(
        __float2bfloat16(v.x - __bfloat162float(hx)),
        __float2bfloat16(v.y - __bfloat162float(hy)));
    p[1024 + 2 * c4 + 1] = __halves2bfloat162(
        __float2bfloat16(v.z - __bfloat162float(hz)),
        __float2bfloat16(v.w - __bfloat162float(hw)));
}

// z=0: W_in -> g_B0, z=1: W_out -> g_B1
__global__ void trans_split(const float* __restrict__ W0,
                            const float* __restrict__ W1) {
    __shared__ float s[32][33];
    const float* W = blockIdx.z ? W1 : W0;
    __nv_bfloat16* T = blockIdx.z ? g_B1 : g_B0;
    int n0 = blockIdx.x * 32, k0 = blockIdx.y * 32;
    int tx = threadIdx.x, ty = threadIdx.y;
#pragma unroll
    for (int i = 0; i < 32; i += 8)
        s[ty + i][tx] = W[(size_t)(k0 + ty + i) * NH + n0 + tx];
    __syncthreads();
#pragma unroll
    for (int i = 0; i < 32; i += 8) {
        float v = s[tx][ty + i];
        __nv_bfloat16 h = __float2bfloat16(v);
        __nv_bfloat16 l = __float2bfloat16(v - __bfloat162float(h));
        size_t o = (size_t)(n0 + ty + i) * KW + k0 + tx;
        T[o] = h;
        T[o + 2048] = l;
    }
}

__global__ void bias_comb(const float* __restrict__ a,
                          const float* __restrict__ b) {
    int i = blockIdx.x * 512 + threadIdx.x;
    if (i < NH) g_bpre[i] = a[i] + b[i];
}

// ---------------- GEMM ------------------------------------------------------
#define BM 128
#define BN 128
#define BK 64
#define STG 3
#define STAGE_B 32768
#define NT (KX / BK)  // 96
#define GEMM_SMEM (STG * STAGE_B + 1024)  // 99328

template <int MODE>  // 0: C=g_pre (t-major) | 1: C=out remap+clamp
__device__ void gemm_body(char* dsm, int cta,
                          const __nv_bfloat16* __restrict__ Ag,
                          const __nv_bfloat16* __restrict__ Bg,
                          const float* __restrict__ bias,
                          float* __restrict__ C) {
    const int by = cta >> 4, bx = cta & 15;
    const int tid = threadIdx.x, lane = tid & 31, wid = tid >> 5;
    const int wm = wid & 1, wn = wid >> 1;

    uint32_t base = (s2u(dsm) + 1023u) & ~1023u;
    const __nv_bfloat16* Abase = Ag + (size_t)(by * BM + (tid >> 3)) * KW +
                                 (tid & 7) * 8;
    const __nv_bfloat16* Bbase = Bg + (size_t)(bx * BN + (tid >> 3)) * KW +
                                 (tid & 7) * 8;

    float acc[4][4][4];
#pragma unroll
    for (int m = 0; m < 4; m++)
#pragma unroll
        for (int n = 0; n < 4; n++)
#pragma unroll
            for (int q = 0; q < 4; q++) acc[m][n][q] = 0.f;

    uint32_t stoff[4];
#pragma unroll
    for (int u = 0; u < 4; u++) {
        int unit = tid + 256 * u;
        stoff[u] = SWZ((uint32_t)((unit >> 3) * 128 + (unit & 7) * 16));
    }

    auto load_stage = [&](int s, int ks) {
        int ka = ((ks & 31) + ((ks >= 64) ? 32 : 0)) * 64;
        int kb = ((ks & 31) + (((ks >> 5) == 1) ? 32 : 0)) * 64;
        uint32_t sb = base + s * STAGE_B;
#pragma unroll
        for (int u = 0; u < 4; u++)
            cpa16(sb + stoff[u], Abase + (size_t)(32 * u) * KW + ka);
#pragma unroll
        for (int u = 0; u < 4; u++)
            cpa16(sb + 16384 + stoff[u], Bbase + (size_t)(32 * u) * KW + kb);
    };

    load_stage(0, 0);
    CP_COMMIT;
    load_stage(1, 1);
    CP_COMMIT;

    uint32_t aoff[4], boff[2];
#pragma unroll
    for (int mt = 0; mt < 4; mt++)
        aoff[mt] = (uint32_t)((wm * 64 + mt * 16 + (lane & 15)) * 128 +
                              (lane >> 4) * 16);
#pragma unroll
    for (int p = 0; p < 2; p++)
        boff[p] = (uint32_t)((wn * 32 + p * 16 + (lane & 15)) * 128 +
                             (lane >> 4) * 16);

    for (int ks = 0; ks < NT; ks++) {
        if (ks < NT - 1) cp_wait1();
        else cp_wait0();
        __syncthreads();
        if (ks + 2 < NT) {
            load_stage((ks + 2) % STG, ks + 2);
            CP_COMMIT;
        }
        const uint32_t sa = base + (ks % STG) * STAGE_B;
        const uint32_t sb = sa + 16384;
#pragma unroll
        for (int k16 = 0; k16 < 4; k16++) {
            uint32_t aF[4][4], bF[4][2];
#pragma unroll
            for (int mt = 0; mt < 4; mt++)
                ldsm4(aF[mt], sa + SWZ(aoff[mt] + k16 * 32));
#pragma unroll
            for (int p = 0; p < 2; p++) {
                uint32_t t[4];
                ldsm4(t, sb + SWZ(boff[p] + k16 * 32));
                bF[2 * p][0] = t[0];
                bF[2 * p][1] = t[2];
                bF[2 * p + 1][0] = t[1];
                bF[2 * p + 1][1] = t[3];
            }
#pragma unroll
            for (int mt = 0; mt < 4; mt++)
#pragma unroll
                for (int nt = 0; nt < 4; nt++)
                    mma16816(acc[mt][nt], aF[mt], bF[nt]);
        }
        __syncthreads();
    }

    const int g = lane >> 2, t4 = lane & 3;
#pragma unroll
    for (int mt = 0; mt < 4; mt++) {
        const int r0 = by * BM + wm * 64 + mt * 16 + g;
        size_t rowbase, rowbase8;
        if (MODE == 0) {
            rowbase = (size_t)r0 * NH;
            rowbase8 = (size_t)(r0 + 8) * NH;
        } else {
            rowbase = (size_t)((r0 & 63) * 64 + (r0 >> 6)) * NH;
            rowbase8 = (size_t)(((r0 + 8) & 63) * 64 + ((r0 + 8) >> 6)) * NH;
        }
#pragma unroll
        for (int nt = 0; nt < 4; nt++) {
            const int c0 = bx * BN + wn * 32 + nt * 8 + t4 * 2;
            float2 bb2 = *(const float2*)&bias[c0];
            float v0 = acc[mt][nt][0] + bb2.x, v1 = acc[mt][nt][1] + bb2.y;
            float v2 = acc[mt][nt][2] + bb2.x, v3 = acc[mt][nt][3] + bb2.y;
            if (MODE == 1) {
                v0 = fminf(fmaxf(v0, 0.f), 1.f);
                v1 = fminf(fmaxf(v1, 0.f), 1.f);
                v2 = fminf(fmaxf(v2, 0.f), 1.f);
                v3 = fminf(fmaxf(v3, 0.f), 1.f);
            }
            float2 w0 = {v0, v1}, w1 = {v2, v3};
            *(float2*)&C[rowbase + c0] = w0;
            *(float2*)&C[rowbase8 + c0] = w1;
        }
    }
}

__global__ void __launch_bounds__(256, 2) gemm0_k() {
    extern __shared__ char dsm[];
    gemm_body<0>(dsm, blockIdx.x, g_Ax, g_B0, g_bpre, g_pre);
}
__global__ void __launch_bounds__(256, 2) gemm1_k(const float* __restrict__ b_out,
                                                  float* __restrict__ out) {
    extern __shared__ char dsm[];
    gemm_body<1>(dsm, blockIdx.x, g_Ah, g_B1, b_out, out);
}

// ---------------- recurrence: 2 half-blocks per batch, 256 threads -----------
// smem floats: skey[20][1024] | sread[20][1024] | spart[20][256] | spre 1024 |
//              sbn 512 | ssim 128 | sprob 128 | sko 32 | sk 32 | sr 24
#define RQ_KEY 0
#define RQ_READ 20480
#define RQ_PART 40960
#define RQ_PRE 46080
#define RQ_BN 47104
#define RQ_SIM 47616
#define RQ_PROB 47744
#define RQ_KO 47872
#define RQ_K 47904
#define RQ_R 47936
#define RECUR_SMEM ((RQ_R + 24) * 4)   // 191,840 B

__global__ void __launch_bounds__(256, 1)
recur_k(const float* __restrict__ h0, const float* __restrict__ b_key,
        const float* __restrict__ W_read, const float* __restrict__ memory,
        const float* __restrict__ W_key) {
    extern __shared__ float rs[];
    float* skey = rs + RQ_KEY;
    float* sread = rs + RQ_READ;
    float* spart = rs + RQ_PART;
    float* spre = rs + RQ_PRE;
    float* sbn = rs + RQ_BN;
    float* ssim = rs + RQ_SIM;
    float* sprob = rs + RQ_PROB;
    float* sko = rs + RQ_KO;
    float* sk = rs + RQ_K;
    float* sr = rs + RQ_R;
    const uint32_t spre_u = s2u(spre);

    const int bid = blockIdx.x;
    const int b = bid >> 1, half = bid & 1;
    const int rowoff = half * HNH;
    const int self = bid, peer = bid ^ 1;
    const int tid = threadIdx.x, lane = tid & 31, warp = tid >> 5;

    // hidden state half in registers: rows rowoff + 4*tid .. +3
    float4 v = ((const float4*)(h0 + (size_t)b * NH + rowoff))[tid];

    // W_key half, j-major
    for (int i = tid; i < MW * HNH; i += 256) {
        int j = i >> 10, rl = i & (HNH - 1);
        skey[i] = W_key[(size_t)(rowoff + rl) * MW + j];
    }
    // W_read half, m-major
    for (int i = tid; i < MW * HNH; i += 256) {
        int m = i >> 10, c = i & (HNH - 1);
        sread[i] = W_read[(size_t)m * NH + rowoff + c];
    }
    for (int i = tid; i < MBK * MN; i += 256) {
        float s = 0.f;
        const float* row = memory + (size_t)i * MW;
#pragma unroll
        for (int m = 0; m < MW; m++) s += row[m] * row[m];
        sbn[i] = sqrtf(s);
    }
    __syncthreads();

    for (int t = 0; t < T_SZ; t++) {
        cpa16(spre_u + tid * 16,
              g_pre + (size_t)(t * 64 + b) * NH + rowoff + tid * 4);
        CP_COMMIT;

        // ---- k partials: own 4 rows from registers, skey via float4 LDS ----
#pragma unroll
        for (int j = 0; j < MW; j++) {
            float4 w = ((const float4*)(skey + j * HNH))[tid];
            spart[j * 256 + tid] =
                v.x * w.x + v.y * w.y + v.z * w.z + v.w * w.w;
        }
        __syncthreads();  // A: partials ready

        // ---- stage2: warp w reduces j = w, w+8, w+16 ----
#pragma unroll
        for (int m = 0; m < 3; m++) {
            const int j = warp + 8 * m;
            if (j < MW) {
                const float* pp = spart + j * 256 + lane;
                float s = pp[0] + pp[32] + pp[64] + pp[96] + pp[128] +
                          pp[160] + pp[192] + pp[224];
#pragma unroll
                for (int o = 16; o > 0; o >>= 1)
                    s += __shfl_xor_sync(0xffffffffu, s, o);
                if (lane == 0) sko[j] = s;
            }
        }
        __syncthreads();  // B: own-half k ready

        // ---- exchange with peer half (warp 0); kpart double-buffered by t&1
        if (warp == 0) {
            float* kp_self = g_kpart + ((size_t)self * 2 + (t & 1)) * MW;
            const float* kp_peer = g_kpart + ((size_t)peer * 2 + (t & 1)) * MW;
            float kv = 0.f;
            if (lane < MW) {
                kv = sko[lane];
                ((volatile float*)kp_self)[lane] = kv;
            }
            __syncwarp();
            __threadfence();
            if (lane == 0) {
                ((volatile int*)g_kflag)[self] = t + 1;
                volatile int* kf = g_kflag;
                while (kf[peer] < t + 1) __nanosleep(64);
            }
            __syncwarp();
            __threadfence();
            if (lane < MW)
                sk[lane] = kv + ((volatile float*)kp_peer)[lane] + b_key[lane];
        }
        __syncthreads();  // C: full k ready

        const int bkx = t & (MBK - 1);
        const float* bank = memory + (size_t)bkx * MN * MW;

        // ---- sim: 8 warps x 16 rows ----
        {
            float kv2 = (lane < MW) ? sk[lane] : 0.f;
            float sq = kv2 * kv2;
#pragma unroll
            for (int o = 16; o > 0; o >>= 1)
                sq += __shfl_xor_sync(0xffffffffu, sq, o);
            const float kn = sqrtf(sq);
            if (lane < 16) {
                const int row = warp * 16 + lane;
                const float4* bn = (const float4*)(bank + (size_t)row * MW);
                float d = 0.f;
#pragma unroll
                for (int j4 = 0; j4 < 5; j4++) {
                    float4 w = __ldg(&bn[j4]);
                    d += sk[j4 * 4 + 0] * w.x + sk[j4 * 4 + 1] * w.y +
                         sk[j4 * 4 + 2] * w.z + sk[j4 * 4 + 3] * w.w;
                }
                ssim[row] = d / (kn * sbn[bkx * MN + row] + 1e-8f);
            }
        }
        __syncthreads();  // D: sim ready

        // ---- softmax over 128 (warp 0) ----
        if (warp == 0) {
            float pv[4];
#pragma unroll
            for (int q = 0; q < 4; q++) pv[q] = ssim[q * 32 + lane];
            float mx = fmaxf(fmaxf(pv[0], pv[1]), fmaxf(pv[2], pv[3]));
#pragma unroll
            for (int o = 16; o > 0; o >>= 1)
                mx = fmaxf(mx, __shfl_xor_sync(0xffffffffu, mx, o));
            float e[4], s = 0.f;
#pragma unroll
            for (int q = 0; q < 4; q++) {
                e[q] = expf(pv[q] - mx);
                s += e[q];
            }
#pragma unroll
            for (int o = 16; o > 0; o >>= 1)
                s += __shfl_xor_sync(0xffffffffu, s, o);
            const float inv = 1.f / s;
#pragma unroll
            for (int q = 0; q < 4; q++) sprob[q * 32 + lane] = e[q] * inv;
        }
        __syncthreads();  // E: prob ready

        // ---- r: warp w handles j = w, w+8, w+16 ----
#pragma unroll
        for (int m = 0; m < 3; m++) {
            const int j = warp + 8 * m;
            if (j < MW) {
                float a = 0.f;
#pragma unroll
                for (int q = 0; q < 4; q++) {
                    const int n = lane + 32 * q;
                    a += sprob[n] * __ldg(bank + (size_t)n * MW + j);
                }
#pragma unroll
                for (int o = 16; o > 0; o >>= 1)
                    a += __shfl_xor_sync(0xffffffffu, a, o);
                if (lane == 0) sr[j] = a;
            }
        }
        __syncthreads();  // F: r ready

        // ---- epilogue: h_new (regs) = relu(pre + r @ W_read_half) ----
        {
            cp_wait0();  // own 16B of spre
            float4 p = ((const float4*)spre)[tid];
#pragma unroll
            for (int m = 0; m < MW; m++) {
                const float rm = sr[m];
                float4 w = ((const float4*)(sread + m * HNH))[tid];
                p.x += rm * w.x; p.y += rm * w.y;
                p.z += rm * w.z; p.w += rm * w.w;
            }
            v.x = fmaxf(p.x, 0.f); v.y = fmaxf(p.y, 0.f);
            v.z = fmaxf(p.z, 0.f); v.w = fmaxf(p.w, 0.f);

            const size_t rowb = (size_t)(t * 64 + b) * KW + rowoff;
            __nv_bfloat16 hx = __float2bfloat16(v.x), hy = __float2bfloat16(v.y);
            __nv_bfloat16 hz = __float2bfloat16(v.z), hw = __float2bfloat16(v.w);
            __nv_bfloat162* ph = (__nv_bfloat162*)(g_Ah + rowb + 4 * tid);
            ph[0] = __halves2bfloat162(hx, hy);
            ph[1] = __halves2bfloat162(hz, hw);
            __nv_bfloat162* pl = (__nv_bfloat162*)(g_Ah + rowb + 2048 + 4 * tid);
            pl[0] = __halves2bfloat162(
                __float2bfloat16(v.x - __bfloat162float(hx)),
                __float2bfloat16(v.y - __bfloat162float(hy)));
            pl[1] = __halves2bfloat162(
                __float2bfloat16(v.z - __bfloat162float(hz)),
                __float2bfloat16(v.w - __bfloat162float(hw)));
        }
        // no trailing barrier needed: all next-step shared writes occur after
        // barriers A..F of the next iteration; spre/regs are per-thread.
    }
}

// ---------------- host -------------------------------------------------------
extern "C" void kernel_launch(void* const* d_in, const int* in_sizes, int n_in,
                              void* d_out, int out_size) {
    const float* x      = (const float*)d_in[0];
    const float* h0     = (const float*)d_in[1];
    const float* W_in   = (const float*)d_in[2];
    const float* b_in   = (const float*)d_in[3];
    const float* W_read = (const float*)d_in[4];
    const float* b_read = (const float*)d_in[5];
    const float* W_out  = (const float*)d_in[6];
    const float* b_out  = (const float*)d_in[7];
    const float* W_key  = (const float*)d_in[8];
    const float* b_key  = (const float*)d_in[9];
    const float* memory = (const float*)d_in[10];
    float* out = (float*)d_out;

    cudaFuncSetAttribute(gemm0_k, cudaFuncAttributeMaxDynamicSharedMemorySize,
                         GEMM_SMEM);
    cudaFuncSetAttribute(gemm1_k, cudaFuncAttributeMaxDynamicSharedMemorySize,
                         GEMM_SMEM);
    cudaFuncSetAttribute(recur_k, cudaFuncAttributeMaxDynamicSharedMemorySize,
                         RECUR_SMEM);

    init_flags<<<1, 128>>>();
    conv_x<<<(M_ROWS * NI / 4 + 255) / 256, 256>>>((const float4*)x);
    trans_split<<<dim3(64, 64, 2), dim3(32, 8)>>>(W_in, W_out);
    bias_comb<<<4, 512>>>(b_in, b_read);

    gemm0_k<<<512, 256, GEMM_SMEM>>>();
    recur_k<<<2 * B_SZ, 256, RECUR_SMEM>>>(h0, b_key, W_read, memory, W_key);
    gemm1_k<<<512, 256, GEMM_SMEM>>>(b_out, out);
}

// round 13
// speedup vs baseline: 1.3452x; 1.3452x over previous
#include <cuda_runtime.h>
#include <cuda_bf16.h>
#include <math.h>
#include <stdint.h>

#define B_SZ 64
#define T_SZ 64
#define NI 2048
#define NH 2048
#define MBK 4
#define MN 128
#define MW 20
#define M_ROWS 4096
#define KW 4096   // compact split width [hi | lo]
#define KX 6144   // logical K (3 terms x 2048)

// ---------------- device scratch (t-major rows: r = t*64 + b) ----------------
__device__ float g_pre[(size_t)M_ROWS * NH];
__device__ float g_bpre[NH];
__device__ __nv_bfloat16 g_Ax[(size_t)M_ROWS * KW];   // x split
__device__ __nv_bfloat16 g_Ah[(size_t)M_ROWS * KW];   // H split
__device__ __nv_bfloat16 g_B0[(size_t)NH * KW];       // W_in^T  [hi|lo]
__device__ __nv_bfloat16 g_B1[(size_t)NH * KW];       // W_out^T [hi|lo]

// ---------------- helpers ----------------------------------------------------
__device__ __forceinline__ uint32_t s2u(const void* p) {
    uint32_t r;
    asm("{ .reg .u64 t; cvta.to.shared.u64 t, %1; cvt.u32.u64 %0, t; }"
        : "=r"(r) : "l"(p));
    return r;
}
#define SWZ(x) ((x) ^ (((x) >> 3) & 0x70))
__device__ __forceinline__ void cpa16(uint32_t s, const void* g) {
    asm volatile("cp.async.cg.shared.global [%0], [%1], 16;" :: "r"(s), "l"(g)
                 : "memory");
}
#define CP_COMMIT asm volatile("cp.async.commit_group;" ::: "memory")
__device__ __forceinline__ void cp_wait1() {
    asm volatile("cp.async.wait_group 1;" ::: "memory");
}
__device__ __forceinline__ void cp_wait0() {
    asm volatile("cp.async.wait_group 0;" ::: "memory");
}
__device__ __forceinline__ void ldsm4(uint32_t* r, uint32_t a) {
    asm volatile("ldmatrix.sync.aligned.m8n8.x4.shared.b16 {%0,%1,%2,%3}, [%4];"
                 : "=r"(r[0]), "=r"(r[1]), "=r"(r[2]), "=r"(r[3]) : "r"(a));
}
__device__ __forceinline__ void mma16816(float* c, const uint32_t* a,
                                         const uint32_t* b) {
    asm volatile(
        "mma.sync.aligned.m16n8k16.row.col.f32.bf16.bf16.f32 "
        "{%0,%1,%2,%3}, {%4,%5,%6,%7}, {%8,%9}, {%0,%1,%2,%3};"
        : "+f"(c[0]), "+f"(c[1]), "+f"(c[2]), "+f"(c[3])
        : "r"(a[0]), "r"(a[1]), "r"(a[2]), "r"(a[3]), "r"(b[0]), "r"(b[1]));
}

// ---------------- small prep kernels -----------------------------------------
__global__ void conv_x(const float4* __restrict__ x4) {
    int i = blockIdx.x * 256 + threadIdx.x;
    if (i >= M_ROWS * NI / 4) return;
    int row = i >> 9, c4 = i & 511;          // input row = b*64 + t
    int b = row >> 6, t = row & 63;
    int orow = t * 64 + b;                   // t-major
    float4 v = x4[i];
    __nv_bfloat16 hx = __float2bfloat16(v.x), hy = __float2bfloat16(v.y);
    __nv_bfloat16 hz = __float2bfloat16(v.z), hw = __float2bfloat16(v.w);
    __nv_bfloat162* p = (__nv_bfloat162*)(g_Ax + (size_t)orow * KW);
    p[2 * c4] = __halves2bfloat162(hx, hy);
    p[2 * c4 + 1] = __halves2bfloat162(hz, hw);
    p[1024 + 2 * c4] = __halves2bfloat162(
        __float2bfloat16(v.x - __bfloat162float(hx)),
        __float2bfloat16(v.y - __bfloat162float(hy)));
    p[1024 + 2 * c4 + 1] = __halves2bfloat162(
        __float2bfloat16(v.z - __bfloat162float(hz)),
        __float2bfloat16(v.w - __bfloat162float(hw)));
}

// z=0: W_in -> g_B0, z=1: W_out -> g_B1
__global__ void trans_split(const float* __restrict__ W0,
                            const float* __restrict__ W1) {
    __shared__ float s[32][33];
    const float* W = blockIdx.z ? W1 : W0;
    __nv_bfloat16* T = blockIdx.z ? g_B1 : g_B0;
    int n0 = blockIdx.x * 32, k0 = blockIdx.y * 32;
    int tx = threadIdx.x, ty = threadIdx.y;
#pragma unroll
    for (int i = 0; i < 32; i += 8)
        s[ty + i][tx] = W[(size_t)(k0 + ty + i) * NH + n0 + tx];
    __syncthreads();
#pragma unroll
    for (int i = 0; i < 32; i += 8) {
        float v = s[tx][ty + i];
        __nv_bfloat16 h = __float2bfloat16(v);
        __nv_bfloat16 l = __float2bfloat16(v - __bfloat162float(h));
        size_t o = (size_t)(n0 + ty + i) * KW + k0 + tx;
        T[o] = h;
        T[o + 2048] = l;
    }
}

__global__ void bias_comb(const float* __restrict__ a,
                          const float* __restrict__ b) {
    int i = blockIdx.x * 512 + threadIdx.x;
    if (i < NH) g_bpre[i] = a[i] + b[i];
}

// ---------------- GEMM ------------------------------------------------------
#define BM 128
#define BN 128
#define BK 64
#define STG 3
#define STAGE_B 32768
#define NT (KX / BK)  // 96
#define GEMM_SMEM (STG * STAGE_B + 1024)  // 99328

template <int MODE>  // 0: C=g_pre (t-major) | 1: C=out remap+clamp
__device__ void gemm_body(char* dsm, int cta,
                          const __nv_bfloat16* __restrict__ Ag,
                          const __nv_bfloat16* __restrict__ Bg,
                          const float* __restrict__ bias,
                          float* __restrict__ C) {
    const int by = cta >> 4, bx = cta & 15;
    const int tid = threadIdx.x, lane = tid & 31, wid = tid >> 5;
    const int wm = wid & 1, wn = wid >> 1;

    uint32_t base = (s2u(dsm) + 1023u) & ~1023u;
    const __nv_bfloat16* Abase = Ag + (size_t)(by * BM + (tid >> 3)) * KW +
                                 (tid & 7) * 8;
    const __nv_bfloat16* Bbase = Bg + (size_t)(bx * BN + (tid >> 3)) * KW +
                                 (tid & 7) * 8;

    float acc[4][4][4];
#pragma unroll
    for (int m = 0; m < 4; m++)
#pragma unroll
        for (int n = 0; n < 4; n++)
#pragma unroll
            for (int q = 0; q < 4; q++) acc[m][n][q] = 0.f;

    uint32_t stoff[4];
#pragma unroll
    for (int u = 0; u < 4; u++) {
        int unit = tid + 256 * u;
        stoff[u] = SWZ((uint32_t)((unit >> 3) * 128 + (unit & 7) * 16));
    }

    auto load_stage = [&](int s, int ks) {
        int ka = ((ks & 31) + ((ks >= 64) ? 32 : 0)) * 64;
        int kb = ((ks & 31) + (((ks >> 5) == 1) ? 32 : 0)) * 64;
        uint32_t sb = base + s * STAGE_B;
#pragma unroll
        for (int u = 0; u < 4; u++)
            cpa16(sb + stoff[u], Abase + (size_t)(32 * u) * KW + ka);
#pragma unroll
        for (int u = 0; u < 4; u++)
            cpa16(sb + 16384 + stoff[u], Bbase + (size_t)(32 * u) * KW + kb);
    };

    load_stage(0, 0);
    CP_COMMIT;
    load_stage(1, 1);
    CP_COMMIT;

    uint32_t aoff[4], boff[2];
#pragma unroll
    for (int mt = 0; mt < 4; mt++)
        aoff[mt] = (uint32_t)((wm * 64 + mt * 16 + (lane & 15)) * 128 +
                              (lane >> 4) * 16);
#pragma unroll
    for (int p = 0; p < 2; p++)
        boff[p] = (uint32_t)((wn * 32 + p * 16 + (lane & 15)) * 128 +
                             (lane >> 4) * 16);

    for (int ks = 0; ks < NT; ks++) {
        if (ks < NT - 1) cp_wait1();
        else cp_wait0();
        __syncthreads();
        if (ks + 2 < NT) {
            load_stage((ks + 2) % STG, ks + 2);
            CP_COMMIT;
        }
        const uint32_t sa = base + (ks % STG) * STAGE_B;
        const uint32_t sb = sa + 16384;
#pragma unroll
        for (int k16 = 0; k16 < 4; k16++) {
            uint32_t aF[4][4], bF[4][2];
#pragma unroll
            for (int mt = 0; mt < 4; mt++)
                ldsm4(aF[mt], sa + SWZ(aoff[mt] + k16 * 32));
#pragma unroll
            for (int p = 0; p < 2; p++) {
                uint32_t t[4];
                ldsm4(t, sb + SWZ(boff[p] + k16 * 32));
                bF[2 * p][0] = t[0];
                bF[2 * p][1] = t[2];
                bF[2 * p + 1][0] = t[1];
                bF[2 * p + 1][1] = t[3];
            }
#pragma unroll
            for (int mt = 0; mt < 4; mt++)
#pragma unroll
                for (int nt = 0; nt < 4; nt++)
                    mma16816(acc[mt][nt], aF[mt], bF[nt]);
        }
        __syncthreads();
    }

    const int g = lane >> 2, t4 = lane & 3;
#pragma unroll
    for (int mt = 0; mt < 4; mt++) {
        const int r0 = by * BM + wm * 64 + mt * 16 + g;
        size_t rowbase, rowbase8;
        if (MODE == 0) {
            rowbase = (size_t)r0 * NH;
            rowbase8 = (size_t)(r0 + 8) * NH;
        } else {
            rowbase = (size_t)((r0 & 63) * 64 + (r0 >> 6)) * NH;
            rowbase8 = (size_t)(((r0 + 8) & 63) * 64 + ((r0 + 8) >> 6)) * NH;
        }
#pragma unroll
        for (int nt = 0; nt < 4; nt++) {
            const int c0 = bx * BN + wn * 32 + nt * 8 + t4 * 2;
            float2 bb2 = *(const float2*)&bias[c0];
            float v0 = acc[mt][nt][0] + bb2.x, v1 = acc[mt][nt][1] + bb2.y;
            float v2 = acc[mt][nt][2] + bb2.x, v3 = acc[mt][nt][3] + bb2.y;
            if (MODE == 1) {
                v0 = fminf(fmaxf(v0, 0.f), 1.f);
                v1 = fminf(fmaxf(v1, 0.f), 1.f);
                v2 = fminf(fmaxf(v2, 0.f), 1.f);
                v3 = fminf(fmaxf(v3, 0.f), 1.f);
            }
            float2 w0 = {v0, v1}, w1 = {v2, v3};
            *(float2*)&C[rowbase + c0] = w0;
            *(float2*)&C[rowbase8 + c0] = w1;
        }
    }
}

__global__ void __launch_bounds__(256, 2) gemm0_k() {
    extern __shared__ char dsm[];
    gemm_body<0>(dsm, blockIdx.x, g_Ax, g_B0, g_bpre, g_pre);
}
__global__ void __launch_bounds__(256, 2) gemm1_k(const float* __restrict__ b_out,
                                                  float* __restrict__ out) {
    extern __shared__ char dsm[];
    gemm_body<1>(dsm, blockIdx.x, g_Ah, g_B1, b_out, out);
}

// ---------------- recurrence: one block/batch, 512 threads, h in regs --------
// smem floats: skey[20][2048] | spart[20][512] | sbank[128*20] | spre 2048 |
//              sbn 512 | ssim 128 | sprob 128 | sk 24 | sr 24
#define RC_KEY 0
#define RC_PART (RC_KEY + MW * NH)    // 40960
#define RC_BANK (RC_PART + MW * 512)  // 51200
#define RC_PRE (RC_BANK + MN * MW)    // 53760
#define RC_BN (RC_PRE + NH)           // 55808
#define RC_SIM (RC_BN + 512)          // 56320
#define RC_PROB (RC_SIM + MN)         // 56448
#define RC_K (RC_PROB + MN)           // 56576
#define RC_R (RC_K + 24)              // 56600
#define RECUR_SMEM ((RC_R + 24) * 4)  // 226,496 B

__global__ void __launch_bounds__(512, 1)
recur_k(const float* __restrict__ h0, const float* __restrict__ b_key,
        const float* __restrict__ W_read, const float* __restrict__ memory,
        const float* __restrict__ W_key) {
    extern __shared__ float rs[];
    float* skey = rs + RC_KEY;
    float* spart = rs + RC_PART;
    float* sbank = rs + RC_BANK;
    float* spre = rs + RC_PRE;
    float* sbn = rs + RC_BN;
    float* ssim = rs + RC_SIM;
    float* sprob = rs + RC_PROB;
    float* sk = rs + RC_K;
    float* sr = rs + RC_R;
    const uint32_t sbank_u = s2u(sbank);
    const uint32_t spre_u = s2u(spre);

    const int b = blockIdx.x;
    const int tid = threadIdx.x;
    const int lane = tid & 31, warp = tid >> 5;

    // hidden state: thread owns rows 4*tid .. 4*tid+3 (registers)
    float4 v = ((const float4*)(h0 + (size_t)b * NH))[tid];

    // W_key j-major: skey[j][r]
    for (int i = tid; i < MW * NH; i += 512) {
        int j = i >> 11, r = i & (NH - 1);
        skey[i] = W_key[(size_t)r * MW + j];
    }
    // bank norms (all 4 banks)
    for (int i = tid; i < MBK * MN; i += 512) {
        float s = 0.f;
        const float* row = memory + (size_t)i * MW;
#pragma unroll
        for (int m = 0; m < MW; m++) s += row[m] * row[m];
        sbn[i] = sqrtf(s);
    }
    __syncthreads();

    for (int t = 0; t < T_SZ; t++) {
        const int bkx = t & (MBK - 1);
        const float* bank = memory + (size_t)bkx * MN * MW;
        // group1: bank tile (10240 B = 640 x 16B chunks)
        for (int i = tid; i < MN * MW / 4; i += 512)
            cpa16(sbank_u + i * 16, bank + i * 4);
        CP_COMMIT;
        // group2: this step's pre row (own 16B chunk)
        cpa16(spre_u + tid * 16, g_pre + (size_t)(t * 64 + b) * NH + tid * 4);
        CP_COMMIT;

        // ---- k partials: 20 x LDS.128 on own consecutive rows ----
#pragma unroll
        for (int j = 0; j < MW; j++) {
            float4 w = *(const float4*)&skey[j * NH + 4 * tid];
            spart[j * 512 + tid] =
                v.x * w.x + v.y * w.y + v.z * w.z + v.w * w.w;
        }
        __syncthreads();  // A: partials ready

        // ---- stage2: warp w reduces j=w; warps 0..3 also j=16+w ----
        {
            int jj = warp;
#pragma unroll
            for (int round = 0; round < 2; round++) {
                if (jj < MW) {
                    const float* pp = spart + jj * 512 + lane;
                    float s = 0.f;
#pragma unroll
                    for (int i = 0; i < 16; i++) s += pp[32 * i];
#pragma unroll
                    for (int o = 16; o > 0; o >>= 1)
                        s += __shfl_xor_sync(0xffffffffu, s, o);
                    if (lane == 0) sk[jj] = s + b_key[jj];
                }
                jj = warp + 16;
            }
        }
        cp_wait1();       // bank tile arrived (spre may still be in flight)
        __syncthreads();  // B: sk + sbank visible to all

        // ---- sim: warps 0..7, 16 rows each, from sbank ----
        if (warp < 8) {
            float kv = (lane < MW) ? sk[lane] : 0.f;
            float sq = kv * kv;
#pragma unroll
            for (int o = 16; o > 0; o >>= 1)
                sq += __shfl_xor_sync(0xffffffffu, sq, o);
            const float kn = sqrtf(sq);
            if (lane < 16) {
                const int row = warp * 16 + lane;
                const float4* bn = (const float4*)(sbank + row * MW);
                float d = 0.f;
#pragma unroll
                for (int j4 = 0; j4 < 5; j4++) {
                    float4 w = bn[j4];
                    d += sk[j4 * 4 + 0] * w.x + sk[j4 * 4 + 1] * w.y +
                         sk[j4 * 4 + 2] * w.z + sk[j4 * 4 + 3] * w.w;
                }
                ssim[row] = d / (kn * sbn[bkx * MN + row] + 1e-8f);
            }
        }
        __syncthreads();  // C: sim ready

        // ---- softmax over 128 (warp 0) ----
        if (warp == 0) {
            float pv[4];
#pragma unroll
            for (int q = 0; q < 4; q++) pv[q] = ssim[q * 32 + lane];
            float mx = fmaxf(fmaxf(pv[0], pv[1]), fmaxf(pv[2], pv[3]));
#pragma unroll
            for (int o = 16; o > 0; o >>= 1)
                mx = fmaxf(mx, __shfl_xor_sync(0xffffffffu, mx, o));
            float e[4], s = 0.f;
#pragma unroll
            for (int q = 0; q < 4; q++) {
                e[q] = expf(pv[q] - mx);
                s += e[q];
            }
#pragma unroll
            for (int o = 16; o > 0; o >>= 1)
                s += __shfl_xor_sync(0xffffffffu, s, o);
            const float inv = 1.f / s;
#pragma unroll
            for (int q = 0; q < 4; q++) sprob[q * 32 + lane] = e[q] * inv;
        }
        __syncthreads();  // D: prob ready

        // ---- r: warps 0..3, each 5 outputs, from sbank ----
        if (warp < 4) {
#pragma unroll
            for (int q = 0; q < 5; q++) {
                const int j = warp * 5 + q;
                float a = 0.f;
#pragma unroll
                for (int m = 0; m < 4; m++) {
                    const int n = lane + 32 * m;
                    a += sprob[n] * sbank[n * MW + j];
                }
#pragma unroll
                for (int o = 16; o > 0; o >>= 1)
                    a += __shfl_xor_sync(0xffffffffu, a, o);
                if (lane == 0) sr[j] = a;
            }
        }
        __syncthreads();  // E: r ready

        // ---- epilogue: h_new (regs) = relu(pre + r @ W_read) ----
        {
            cp_wait0();  // own spre chunk ready (self-visible)
            float4 p = ((const float4*)spre)[tid];
#pragma unroll
            for (int m = 0; m < MW; m++) {
                const float rm = sr[m];
                float4 w = __ldg(&((const float4*)W_read)[m * (NH / 4) + tid]);
                p.x += rm * w.x; p.y += rm * w.y;
                p.z += rm * w.z; p.w += rm * w.w;
            }
            v.x = fmaxf(p.x, 0.f); v.y = fmaxf(p.y, 0.f);
            v.z = fmaxf(p.z, 0.f); v.w = fmaxf(p.w, 0.f);

            const size_t rowb = (size_t)(t * 64 + b) * KW;
            __nv_bfloat16 hx = __float2bfloat16(v.x), hy = __float2bfloat16(v.y);
            __nv_bfloat16 hz = __float2bfloat16(v.z), hw = __float2bfloat16(v.w);
            __nv_bfloat162* ph = (__nv_bfloat162*)(g_Ah + rowb + 4 * tid);
            ph[0] = __halves2bfloat162(hx, hy);
            ph[1] = __halves2bfloat162(hz, hw);
            __nv_bfloat162* pl = (__nv_bfloat162*)(g_Ah + rowb + 2048 + 4 * tid);
            pl[0] = __halves2bfloat162(
                __float2bfloat16(v.x - __bfloat162float(hx)),
                __float2bfloat16(v.y - __bfloat162float(hy)));
            pl[1] = __halves2bfloat162(
                __float2bfloat16(v.z - __bfloat162float(hz)),
                __float2bfloat16(v.w - __bfloat162float(hw)));
        }
        // no trailing barrier: every next-step shared write happens after a
        // subsequent barrier (A..E); sbank refill is issued post-E reads by
        // barrier-ordering (all r-phase reads precede E; refill follows E).
    }
}

// ---------------- host -------------------------------------------------------
extern "C" void kernel_launch(void* const* d_in, const int* in_sizes, int n_in,
                              void* d_out, int out_size) {
    const float* x      = (const float*)d_in[0];
    const float* h0     = (const float*)d_in[1];
    const float* W_in   = (const float*)d_in[2];
    const float* b_in   = (const float*)d_in[3];
    const float* W_read = (const float*)d_in[4];
    const float* b_read = (const float*)d_in[5];
    const float* W_out  = (const float*)d_in[6];
    const float* b_out  = (const float*)d_in[7];
    const float* W_key  = (const float*)d_in[8];
    const float* b_key  = (const float*)d_in[9];
    const float* memory = (const float*)d_in[10];
    float* out = (float*)d_out;

    cudaFuncSetAttribute(gemm0_k, cudaFuncAttributeMaxDynamicSharedMemorySize,
                         GEMM_SMEM);
    cudaFuncSetAttribute(gemm1_k, cudaFuncAttributeMaxDynamicSharedMemorySize,
                         GEMM_SMEM);
    cudaFuncSetAttribute(recur_k, cudaFuncAttributeMaxDynamicSharedMemorySize,
                         RECUR_SMEM);

    conv_x<<<(M_ROWS * NI / 4 + 255) / 256, 256>>>((const float4*)x);
    trans_split<<<dim3(64, 64, 2), dim3(32, 8)>>>(W_in, W_out);
    bias_comb<<<4, 512>>>(b_in, b_read);

    gemm0_k<<<512, 256, GEMM_SMEM>>>();
    recur_k<<<B_SZ, 512, RECUR_SMEM>>>(h0, b_key, W_read, memory, W_key);
    gemm1_k<<<512, 256, GEMM_SMEM>>>(b_out, out);
}

// round 14
// speedup vs baseline: 1.7435x; 1.2961x over previous
#include <cuda_runtime.h>
#include <cuda_fp16.h>
#include <math.h>
#include <stdint.h>

#define B_SZ 64
#define T_SZ 64
#define NI 2048
#define NH 2048
#define MBK 4
#define MN 128
#define MW 20
#define M_ROWS 4096
#define KW 4096   // A split width [hi | lo] (fp16)
#define KB 2048   // B width (hi only)
#define KXT 4096  // logical K of the split GEMM

// ---------------- device scratch (t-major rows: r = t*64 + b) ----------------
__device__ float g_pre[(size_t)M_ROWS * NH];
__device__ float g_bpre[NH];
__device__ __half g_Ax[(size_t)M_ROWS * KW];   // x split [hi|lo]
__device__ __half g_Ah[(size_t)M_ROWS * KW];   // H split [hi|lo]
__device__ __half g_B0[(size_t)NH * KB];       // W_in^T  hi
__device__ __half g_B1[(size_t)NH * KB];       // W_out^T hi

// ---------------- helpers ----------------------------------------------------
__device__ __forceinline__ uint32_t s2u(const void* p) {
    uint32_t r;
    asm("{ .reg .u64 t; cvta.to.shared.u64 t, %1; cvt.u32.u64 %0, t; }"
        : "=r"(r) : "l"(p));
    return r;
}
#define SWZ(x) ((x) ^ (((x) >> 3) & 0x70))
__device__ __forceinline__ void cpa16(uint32_t s, const void* g) {
    asm volatile("cp.async.cg.shared.global [%0], [%1], 16;" :: "r"(s), "l"(g)
                 : "memory");
}
#define CP_COMMIT asm volatile("cp.async.commit_group;" ::: "memory")
__device__ __forceinline__ void cp_wait1() {
    asm volatile("cp.async.wait_group 1;" ::: "memory");
}
__device__ __forceinline__ void cp_wait0() {
    asm volatile("cp.async.wait_group 0;" ::: "memory");
}
__device__ __forceinline__ void ldsm4(uint32_t* r, uint32_t a) {
    asm volatile("ldmatrix.sync.aligned.m8n8.x4.shared.b16 {%0,%1,%2,%3}, [%4];"
                 : "=r"(r[0]), "=r"(r[1]), "=r"(r[2]), "=r"(r[3]) : "r"(a));
}
__device__ __forceinline__ void mma16816(float* c, const uint32_t* a,
                                         const uint32_t* b) {
    asm volatile(
        "mma.sync.aligned.m16n8k16.row.col.f32.f16.f16.f32 "
        "{%0,%1,%2,%3}, {%4,%5,%6,%7}, {%8,%9}, {%0,%1,%2,%3};"
        : "+f"(c[0]), "+f"(c[1]), "+f"(c[2]), "+f"(c[3])
        : "r"(a[0]), "r"(a[1]), "r"(a[2]), "r"(a[3]), "r"(b[0]), "r"(b[1]));
}

// ---------------- small prep kernels -----------------------------------------
__global__ void conv_x(const float4* __restrict__ x4) {
    int i = blockIdx.x * 256 + threadIdx.x;
    if (i >= M_ROWS * NI / 4) return;
    int row = i >> 9, c4 = i & 511;          // input row = b*64 + t
    int b = row >> 6, t = row & 63;
    int orow = t * 64 + b;                   // t-major
    float4 v = x4[i];
    __half hx = __float2half_rn(v.x), hy = __float2half_rn(v.y);
    __half hz = __float2half_rn(v.z), hw = __float2half_rn(v.w);
    __half2* p = (__half2*)(g_Ax + (size_t)orow * KW);
    p[2 * c4] = __halves2half2(hx, hy);
    p[2 * c4 + 1] = __halves2half2(hz, hw);
    p[1024 + 2 * c4] = __halves2half2(
        __float2half_rn(v.x - __half2float(hx)),
        __float2half_rn(v.y - __half2float(hy)));
    p[1024 + 2 * c4 + 1] = __halves2half2(
        __float2half_rn(v.z - __half2float(hz)),
        __float2half_rn(v.w - __half2float(hw)));
}

// z=0: W_in -> g_B0, z=1: W_out -> g_B1 (hi only)
__global__ void trans_split(const float* __restrict__ W0,
                            const float* __restrict__ W1) {
    __shared__ float s[32][33];
    const float* W = blockIdx.z ? W1 : W0;
    __half* T = blockIdx.z ? g_B1 : g_B0;
    int n0 = blockIdx.x * 32, k0 = blockIdx.y * 32;
    int tx = threadIdx.x, ty = threadIdx.y;
#pragma unroll
    for (int i = 0; i < 32; i += 8)
        s[ty + i][tx] = W[(size_t)(k0 + ty + i) * NH + n0 + tx];
    __syncthreads();
#pragma unroll
    for (int i = 0; i < 32; i += 8) {
        T[(size_t)(n0 + ty + i) * KB + k0 + tx] = __float2half_rn(s[tx][ty + i]);
    }
}

__global__ void bias_comb(const float* __restrict__ a,
                          const float* __restrict__ b) {
    int i = blockIdx.x * 512 + threadIdx.x;
    if (i < NH) g_bpre[i] = a[i] + b[i];
}

// ---------------- GEMM ------------------------------------------------------
#define BM 128
#define BN 128
#define BK 64
#define STG 3
#define STAGE_B 32768
#define NT (KXT / BK)  // 64
#define GEMM_SMEM (STG * STAGE_B + 1024)  // 99328

template <int MODE>  // 0: C=g_pre (t-major) | 1: C=out remap+clamp
__device__ void gemm_body(char* dsm, int cta,
                          const __half* __restrict__ Ag,
                          const __half* __restrict__ Bg,
                          const float* __restrict__ bias,
                          float* __restrict__ C) {
    const int by = cta >> 4, bx = cta & 15;
    const int tid = threadIdx.x, lane = tid & 31, wid = tid >> 5;
    const int wm = wid & 1, wn = wid >> 1;

    uint32_t base = (s2u(dsm) + 1023u) & ~1023u;
    const __half* Abase = Ag + (size_t)(by * BM + (tid >> 3)) * KW +
                          (tid & 7) * 8;
    const __half* Bbase = Bg + (size_t)(bx * BN + (tid >> 3)) * KB +
                          (tid & 7) * 8;

    float acc[4][4][4];
#pragma unroll
    for (int m = 0; m < 4; m++)
#pragma unroll
        for (int n = 0; n < 4; n++)
#pragma unroll
            for (int q = 0; q < 4; q++) acc[m][n][q] = 0.f;

    uint32_t stoff[4];
#pragma unroll
    for (int u = 0; u < 4; u++) {
        int unit = tid + 256 * u;
        stoff[u] = SWZ((uint32_t)((unit >> 3) * 128 + (unit & 7) * 16));
    }

    // A covers [Ah|Al] via ka = ks*64; B reuses hi via kb = (ks&31)*64
    auto load_stage = [&](int s, int ks) {
        int ka = ks * 64;
        int kb = (ks & 31) * 64;
        uint32_t sb = base + s * STAGE_B;
#pragma unroll
        for (int u = 0; u < 4; u++)
            cpa16(sb + stoff[u], Abase + (size_t)(32 * u) * KW + ka);
#pragma unroll
        for (int u = 0; u < 4; u++)
            cpa16(sb + 16384 + stoff[u], Bbase + (size_t)(32 * u) * KB + kb);
    };

    load_stage(0, 0);
    CP_COMMIT;
    load_stage(1, 1);
    CP_COMMIT;

    uint32_t aoff[4], boff[2];
#pragma unroll
    for (int mt = 0; mt < 4; mt++)
        aoff[mt] = (uint32_t)((wm * 64 + mt * 16 + (lane & 15)) * 128 +
                              (lane >> 4) * 16);
#pragma unroll
    for (int p = 0; p < 2; p++)
        boff[p] = (uint32_t)((wn * 32 + p * 16 + (lane & 15)) * 128 +
                             (lane >> 4) * 16);

    for (int ks = 0; ks < NT; ks++) {
        if (ks < NT - 1) cp_wait1();
        else cp_wait0();
        __syncthreads();  // single barrier per iteration (see ordering proof)
        if (ks + 2 < NT) {
            load_stage((ks + 2) % STG, ks + 2);
            CP_COMMIT;
        }
        const uint32_t sa = base + (ks % STG) * STAGE_B;
        const uint32_t sb = sa + 16384;
#pragma unroll
        for (int k16 = 0; k16 < 4; k16++) {
            uint32_t aF[4][4], bF[4][2];
#pragma unroll
            for (int mt = 0; mt < 4; mt++)
                ldsm4(aF[mt], sa + SWZ(aoff[mt] + k16 * 32));
#pragma unroll
            for (int p = 0; p < 2; p++) {
                uint32_t t[4];
                ldsm4(t, sb + SWZ(boff[p] + k16 * 32));
                bF[2 * p][0] = t[0];
                bF[2 * p][1] = t[2];
                bF[2 * p + 1][0] = t[1];
                bF[2 * p + 1][1] = t[3];
            }
#pragma unroll
            for (int mt = 0; mt < 4; mt++)
#pragma unroll
                for (int nt = 0; nt < 4; nt++)
                    mma16816(acc[mt][nt], aF[mt], bF[nt]);
        }
    }

    const int g = lane >> 2, t4 = lane & 3;
#pragma unroll
    for (int mt = 0; mt < 4; mt++) {
        const int r0 = by * BM + wm * 64 + mt * 16 + g;
        size_t rowbase, rowbase8;
        if (MODE == 0) {
            rowbase = (size_t)r0 * NH;
            rowbase8 = (size_t)(r0 + 8) * NH;
        } else {
            rowbase = (size_t)((r0 & 63) * 64 + (r0 >> 6)) * NH;
            rowbase8 = (size_t)(((r0 + 8) & 63) * 64 + ((r0 + 8) >> 6)) * NH;
        }
#pragma unroll
        for (int nt = 0; nt < 4; nt++) {
            const int c0 = bx * BN + wn * 32 + nt * 8 + t4 * 2;
            float2 bb2 = *(const float2*)&bias[c0];
            float v0 = acc[mt][nt][0] + bb2.x, v1 = acc[mt][nt][1] + bb2.y;
            float v2 = acc[mt][nt][2] + bb2.x, v3 = acc[mt][nt][3] + bb2.y;
            if (MODE == 1) {
                v0 = fminf(fmaxf(v0, 0.f), 1.f);
                v1 = fminf(fmaxf(v1, 0.f), 1.f);
                v2 = fminf(fmaxf(v2, 0.f), 1.f);
                v3 = fminf(fmaxf(v3, 0.f), 1.f);
            }
            float2 w0 = {v0, v1}, w1 = {v2, v3};
            *(float2*)&C[rowbase + c0] = w0;
            *(float2*)&C[rowbase8 + c0] = w1;
        }
    }
}

__global__ void __launch_bounds__(256, 2) gemm0_k() {
    extern __shared__ char dsm[];
    gemm_body<0>(dsm, blockIdx.x, g_Ax, g_B0, g_bpre, g_pre);
}
__global__ void __launch_bounds__(256, 2) gemm1_k(const float* __restrict__ b_out,
                                                  float* __restrict__ out) {
    extern __shared__ char dsm[];
    gemm_body<1>(dsm, blockIdx.x, g_Ah, g_B1, b_out, out);
}

// ---------------- recurrence: one block/batch, 512 threads, h in regs --------
// smem floats: skey[20][2048] | spart[20][512] | sbank[128*20] | spre 2048 |
//              sbn 512 | ssim 128 | sprob 128 | sk 24 | sr 24
#define RC_KEY 0
#define RC_PART (RC_KEY + MW * NH)    // 40960
#define RC_BANK (RC_PART + MW * 512)  // 51200
#define RC_PRE (RC_BANK + MN * MW)    // 53760
#define RC_BN (RC_PRE + NH)           // 55808
#define RC_SIM (RC_BN + 512)          // 56320
#define RC_PROB (RC_SIM + MN)         // 56448
#define RC_K (RC_PROB + MN)           // 56576
#define RC_R (RC_K + 24)              // 56600
#define RECUR_SMEM ((RC_R + 24) * 4)  // 226,496 B

__global__ void __launch_bounds__(512, 1)
recur_k(const float* __restrict__ h0, const float* __restrict__ b_key,
        const float* __restrict__ W_read, const float* __restrict__ memory,
        const float* __restrict__ W_key) {
    extern __shared__ float rs[];
    float* skey = rs + RC_KEY;
    float* spart = rs + RC_PART;
    float* sbank = rs + RC_BANK;
    float* spre = rs + RC_PRE;
    float* sbn = rs + RC_BN;
    float* ssim = rs + RC_SIM;
    float* sprob = rs + RC_PROB;
    float* sk = rs + RC_K;
    float* sr = rs + RC_R;
    const uint32_t sbank_u = s2u(sbank);
    const uint32_t spre_u = s2u(spre);

    const int b = blockIdx.x;
    const int tid = threadIdx.x;
    const int lane = tid & 31, warp = tid >> 5;

    // hidden state: thread owns rows 4*tid .. 4*tid+3 (registers)
    float4 v = ((const float4*)(h0 + (size_t)b * NH))[tid];

    // W_key j-major: skey[j][r]
    for (int i = tid; i < MW * NH; i += 512) {
        int j = i >> 11, r = i & (NH - 1);
        skey[i] = W_key[(size_t)r * MW + j];
    }
    // bank norms (all 4 banks)
    for (int i = tid; i < MBK * MN; i += 512) {
        float s = 0.f;
        const float* row = memory + (size_t)i * MW;
#pragma unroll
        for (int m = 0; m < MW; m++) s += row[m] * row[m];
        sbn[i] = sqrtf(s);
    }
    __syncthreads();

    for (int t = 0; t < T_SZ; t++) {
        const int bkx = t & (MBK - 1);
        const float* bank = memory + (size_t)bkx * MN * MW;
        // group1: bank tile (10240 B = 640 x 16B chunks)
        for (int i = tid; i < MN * MW / 4; i += 512)
            cpa16(sbank_u + i * 16, bank + i * 4);
        CP_COMMIT;
        // group2: this step's pre row (own 16B chunk)
        cpa16(spre_u + tid * 16, g_pre + (size_t)(t * 64 + b) * NH + tid * 4);
        CP_COMMIT;

        // ---- k partials: 20 x LDS.128 on own consecutive rows ----
#pragma unroll
        for (int j = 0; j < MW; j++) {
            float4 w = *(const float4*)&skey[j * NH + 4 * tid];
            spart[j * 512 + tid] =
                v.x * w.x + v.y * w.y + v.z * w.z + v.w * w.w;
        }
        __syncthreads();  // A: partials ready

        // ---- stage2: warp w reduces j=w; warps 0..3 also j=16+w ----
        {
            int jj = warp;
#pragma unroll
            for (int round = 0; round < 2; round++) {
                if (jj < MW) {
                    const float* pp = spart + jj * 512 + lane;
                    float s = 0.f;
#pragma unroll
                    for (int i = 0; i < 16; i++) s += pp[32 * i];
#pragma unroll
                    for (int o = 16; o > 0; o >>= 1)
                        s += __shfl_xor_sync(0xffffffffu, s, o);
                    if (lane == 0) sk[jj] = s + b_key[jj];
                }
                jj = warp + 16;
            }
        }
        cp_wait1();       // bank tile arrived (spre may still be in flight)
        __syncthreads();  // B: sk + sbank visible to all

        // ---- sim: warps 0..7, 16 rows each, from sbank ----
        if (warp < 8) {
            float kv = (lane < MW) ? sk[lane] : 0.f;
            float sq = kv * kv;
#pragma unroll
            for (int o = 16; o > 0; o >>= 1)
                sq += __shfl_xor_sync(0xffffffffu, sq, o);
            const float kn = sqrtf(sq);
            if (lane < 16) {
                const int row = warp * 16 + lane;
                const float4* bn = (const float4*)(sbank + row * MW);
                float d = 0.f;
#pragma unroll
                for (int j4 = 0; j4 < 5; j4++) {
                    float4 w = bn[j4];
                    d += sk[j4 * 4 + 0] * w.x + sk[j4 * 4 + 1] * w.y +
                         sk[j4 * 4 + 2] * w.z + sk[j4 * 4 + 3] * w.w;
                }
                ssim[row] = d / (kn * sbn[bkx * MN + row] + 1e-8f);
            }
        }
        __syncthreads();  // C: sim ready

        // ---- softmax over 128 (warp 0) ----
        if (warp == 0) {
            float pv[4];
#pragma unroll
            for (int q = 0; q < 4; q++) pv[q] = ssim[q * 32 + lane];
            float mx = fmaxf(fmaxf(pv[0], pv[1]), fmaxf(pv[2], pv[3]));
#pragma unroll
            for (int o = 16; o > 0; o >>= 1)
                mx = fmaxf(mx, __shfl_xor_sync(0xffffffffu, mx, o));
            float e[4], s = 0.f;
#pragma unroll
            for (int q = 0; q < 4; q++) {
                e[q] = expf(pv[q] - mx);
                s += e[q];
            }
#pragma unroll
            for (int o = 16; o > 0; o >>= 1)
                s += __shfl_xor_sync(0xffffffffu, s, o);
            const float inv = 1.f / s;
#pragma unroll
            for (int q = 0; q < 4; q++) sprob[q * 32 + lane] = e[q] * inv;
        }
        __syncthreads();  // D: prob ready

        // ---- r: warps 0..3, each 5 outputs, from sbank ----
        if (warp < 4) {
#pragma unroll
            for (int q = 0; q < 5; q++) {
                const int j = warp * 5 + q;
                float a = 0.f;
#pragma unroll
                for (int m = 0; m < 4; m++) {
                    const int n = lane + 32 * m;
                    a += sprob[n] * sbank[n * MW + j];
                }
#pragma unroll
                for (int o = 16; o > 0; o >>= 1)
                    a += __shfl_xor_sync(0xffffffffu, a, o);
                if (lane == 0) sr[j] = a;
            }
        }
        __syncthreads();  // E: r ready

        // ---- epilogue: h_new (regs) = relu(pre + r @ W_read) ----
        {
            cp_wait0();  // own spre chunk ready (self-visible)
            float4 p = ((const float4*)spre)[tid];
#pragma unroll
            for (int m = 0; m < MW; m++) {
                const float rm = sr[m];
                float4 w = __ldg(&((const float4*)W_read)[m * (NH / 4) + tid]);
                p.x += rm * w.x; p.y += rm * w.y;
                p.z += rm * w.z; p.w += rm * w.w;
            }
            v.x = fmaxf(p.x, 0.f); v.y = fmaxf(p.y, 0.f);
            v.z = fmaxf(p.z, 0.f); v.w = fmaxf(p.w, 0.f);

            const size_t rowb = (size_t)(t * 64 + b) * KW;
            __half hx = __float2half_rn(v.x), hy = __float2half_rn(v.y);
            __half hz = __float2half_rn(v.z), hw = __float2half_rn(v.w);
            __half2* ph = (__half2*)(g_Ah + rowb + 4 * tid);
            ph[0] = __halves2half2(hx, hy);
            ph[1] = __halves2half2(hz, hw);
            __half2* pl = (__half2*)(g_Ah + rowb + 2048 + 4 * tid);
            pl[0] = __halves2half2(
                __float2half_rn(v.x - __half2float(hx)),
                __float2half_rn(v.y - __half2float(hy)));
            pl[1] = __halves2half2(
                __float2half_rn(v.z - __half2float(hz)),
                __float2half_rn(v.w - __half2float(hw)));
        }
        // no trailing barrier: every next-step shared write happens after a
        // subsequent barrier (A..E).
    }
}

// ---------------- host -------------------------------------------------------
extern "C" void kernel_launch(void* const* d_in, const int* in_sizes, int n_in,
                              void* d_out, int out_size) {
    const float* x      = (const float*)d_in[0];
    const float* h0     = (const float*)d_in[1];
    const float* W_in   = (const float*)d_in[2];
    const float* b_in   = (const float*)d_in[3];
    const float* W_read = (const float*)d_in[4];
    const float* b_read = (const float*)d_in[5];
    const float* W_out  = (const float*)d_in[6];
    const float* b_out  = (const float*)d_in[7];
    const float* W_key  = (const float*)d_in[8];
    const float* b_key  = (const float*)d_in[9];
    const float* memory = (const float*)d_in[10];
    float* out = (float*)d_out;

    cudaFuncSetAttribute(gemm0_k, cudaFuncAttributeMaxDynamicSharedMemorySize,
                         GEMM_SMEM);
    cudaFuncSetAttribute(gemm1_k, cudaFuncAttributeMaxDynamicSharedMemorySize,
                         GEMM_SMEM);
    cudaFuncSetAttribute(recur_k, cudaFuncAttributeMaxDynamicSharedMemorySize,
                         RECUR_SMEM);

    conv_x<<<(M_ROWS * NI / 4 + 255) / 256, 256>>>((const float4*)x);
    trans_split<<<dim3(64, 64, 2), dim3(32, 8)>>>(W_in, W_out);
    bias_comb<<<4, 512>>>(b_in, b_read);

    gemm0_k<<<512, 256, GEMM_SMEM>>>();
    recur_k<<<B_SZ, 512, RECUR_SMEM>>>(h0, b_key, W_read, memory, W_key);
    gemm1_k<<<512, 256, GEMM_SMEM>>>(b_out, out);
}

// round 16
// speedup vs baseline: 1.9083x; 1.0945x over previous
#include <cuda_runtime.h>
#include <cuda_fp16.h>
#include <math.h>
#include <stdint.h>

#define B_SZ 64
#define T_SZ 64
#define NI 2048
#define NH 2048
#define MBK 4
#define MN 128
#define MW 20
#define M_ROWS 4096
#define KW 4096   // A split width [hi | lo] (fp16)
#define KB 2048   // B width (hi only)
#define KXT 4096  // logical K of the split GEMM

// ---------------- device scratch (t-major rows: r = t*64 + b) ----------------
__device__ float g_pre[(size_t)M_ROWS * NH];
__device__ float g_bpre[NH];
__device__ __half g_Ax[(size_t)M_ROWS * KW];   // x split [hi|lo]
__device__ __half g_Ah[(size_t)M_ROWS * KW];   // H split [hi|lo]
__device__ __half g_B0[(size_t)NH * KB];       // W_in^T  hi
__device__ __half g_B1[(size_t)NH * KB];       // W_out^T hi

// ---------------- helpers ----------------------------------------------------
__device__ __forceinline__ uint32_t s2u(const void* p) {
    uint32_t r;
    asm("{ .reg .u64 t; cvta.to.shared.u64 t, %1; cvt.u32.u64 %0, t; }"
        : "=r"(r) : "l"(p));
    return r;
}
#define SWZ(x) ((x) ^ (((x) >> 3) & 0x70))
__device__ __forceinline__ void cpa16(uint32_t s, const void* g) {
    asm volatile("cp.async.cg.shared.global [%0], [%1], 16;" :: "r"(s), "l"(g)
                 : "memory");
}
#define CP_COMMIT asm volatile("cp.async.commit_group;" ::: "memory")
__device__ __forceinline__ void cp_wait1() {
    asm volatile("cp.async.wait_group 1;" ::: "memory");
}
__device__ __forceinline__ void cp_wait0() {
    asm volatile("cp.async.wait_group 0;" ::: "memory");
}
__device__ __forceinline__ void ldsm4(uint32_t* r, uint32_t a) {
    asm volatile("ldmatrix.sync.aligned.m8n8.x4.shared.b16 {%0,%1,%2,%3}, [%4];"
                 : "=r"(r[0]), "=r"(r[1]), "=r"(r[2]), "=r"(r[3]) : "r"(a));
}
__device__ __forceinline__ void mma16816(float* c, const uint32_t* a,
                                         const uint32_t* b) {
    asm volatile(
        "mma.sync.aligned.m16n8k16.row.col.f32.f16.f16.f32 "
        "{%0,%1,%2,%3}, {%4,%5,%6,%7}, {%8,%9}, {%0,%1,%2,%3};"
        : "+f"(c[0]), "+f"(c[1]), "+f"(c[2]), "+f"(c[3])
        : "r"(a[0]), "r"(a[1]), "r"(a[2]), "r"(a[3]), "r"(b[0]), "r"(b[1]));
}

// ---------------- small prep kernels -----------------------------------------
__global__ void conv_x(const float4* __restrict__ x4) {
    int i = blockIdx.x * 256 + threadIdx.x;
    if (i >= M_ROWS * NI / 4) return;
    int row = i >> 9, c4 = i & 511;          // input row = b*64 + t
    int b = row >> 6, t = row & 63;
    int orow = t * 64 + b;                   // t-major
    float4 v = x4[i];
    __half hx = __float2half_rn(v.x), hy = __float2half_rn(v.y);
    __half hz = __float2half_rn(v.z), hw = __float2half_rn(v.w);
    __half2* p = (__half2*)(g_Ax + (size_t)orow * KW);
    p[2 * c4] = __halves2half2(hx, hy);
    p[2 * c4 + 1] = __halves2half2(hz, hw);
    p[1024 + 2 * c4] = __halves2half2(
        __float2half_rn(v.x - __half2float(hx)),
        __float2half_rn(v.y - __half2float(hy)));
    p[1024 + 2 * c4 + 1] = __halves2half2(
        __float2half_rn(v.z - __half2float(hz)),
        __float2half_rn(v.w - __half2float(hw)));
}

// z=0: W_in -> g_B0, z=1: W_out -> g_B1 (hi only)
__global__ void trans_split(const float* __restrict__ W0,
                            const float* __restrict__ W1) {
    __shared__ float s[32][33];
    const float* W = blockIdx.z ? W1 : W0;
    __half* T = blockIdx.z ? g_B1 : g_B0;
    int n0 = blockIdx.x * 32, k0 = blockIdx.y * 32;
    int tx = threadIdx.x, ty = threadIdx.y;
#pragma unroll
    for (int i = 0; i < 32; i += 8)
        s[ty + i][tx] = W[(size_t)(k0 + ty + i) * NH + n0 + tx];
    __syncthreads();
#pragma unroll
    for (int i = 0; i < 32; i += 8) {
        T[(size_t)(n0 + ty + i) * KB + k0 + tx] = __float2half_rn(s[tx][ty + i]);
    }
}

__global__ void bias_comb(const float* __restrict__ a,
                          const float* __restrict__ b) {
    int i = blockIdx.x * 512 + threadIdx.x;
    if (i < NH) g_bpre[i] = a[i] + b[i];
}

// ---------------- GEMM ------------------------------------------------------
#define BM 128
#define BN 128
#define BK 64
#define STG 3
#define STAGE_B 32768
#define NT (KXT / BK)  // 64
#define GEMM_SMEM (STG * STAGE_B + 1024)  // 99328

template <int MODE>  // 0: C=g_pre (t-major) | 1: C=out remap+clamp
__device__ void gemm_body(char* dsm, int cta,
                          const __half* __restrict__ Ag,
                          const __half* __restrict__ Bg,
                          const float* __restrict__ bias,
                          float* __restrict__ C) {
    const int by = cta >> 4, bx = cta & 15;
    const int tid = threadIdx.x, lane = tid & 31, wid = tid >> 5;
    const int wm = wid & 1, wn = wid >> 1;

    uint32_t base = (s2u(dsm) + 1023u) & ~1023u;
    const __half* Abase = Ag + (size_t)(by * BM + (tid >> 3)) * KW +
                          (tid & 7) * 8;
    const __half* Bbase = Bg + (size_t)(bx * BN + (tid >> 3)) * KB +
                          (tid & 7) * 8;

    float acc[4][4][4];
#pragma unroll
    for (int m = 0; m < 4; m++)
#pragma unroll
        for (int n = 0; n < 4; n++)
#pragma unroll
            for (int q = 0; q < 4; q++) acc[m][n][q] = 0.f;

    uint32_t stoff[4];
#pragma unroll
    for (int u = 0; u < 4; u++) {
        int unit = tid + 256 * u;
        stoff[u] = SWZ((uint32_t)((unit >> 3) * 128 + (unit & 7) * 16));
    }

    // A covers [Ah|Al] via ka = ks*64; B reuses hi via kb = (ks&31)*64
    auto load_stage = [&](int s, int ks) {
        int ka = ks * 64;
        int kb = (ks & 31) * 64;
        uint32_t sb = base + s * STAGE_B;
#pragma unroll
        for (int u = 0; u < 4; u++)
            cpa16(sb + stoff[u], Abase + (size_t)(32 * u) * KW + ka);
#pragma unroll
        for (int u = 0; u < 4; u++)
            cpa16(sb + 16384 + stoff[u], Bbase + (size_t)(32 * u) * KB + kb);
    };

    load_stage(0, 0);
    CP_COMMIT;
    load_stage(1, 1);
    CP_COMMIT;

    uint32_t aoff[4], boff[2];
#pragma unroll
    for (int mt = 0; mt < 4; mt++)
        aoff[mt] = (uint32_t)((wm * 64 + mt * 16 + (lane & 15)) * 128 +
                              (lane >> 4) * 16);
#pragma unroll
    for (int p = 0; p < 2; p++)
        boff[p] = (uint32_t)((wn * 32 + p * 16 + (lane & 15)) * 128 +
                             (lane >> 4) * 16);

    for (int ks = 0; ks < NT; ks++) {
        if (ks < NT - 1) cp_wait1();
        else cp_wait0();
        __syncthreads();
        if (ks + 2 < NT) {
            load_stage((ks + 2) % STG, ks + 2);
            CP_COMMIT;
        }
        const uint32_t sa = base + (ks % STG) * STAGE_B;
        const uint32_t sb = sa + 16384;
#pragma unroll
        for (int k16 = 0; k16 < 4; k16++) {
            uint32_t aF[4][4], bF[4][2];
#pragma unroll
            for (int mt = 0; mt < 4; mt++)
                ldsm4(aF[mt], sa + SWZ(aoff[mt] + k16 * 32));
#pragma unroll
            for (int p = 0; p < 2; p++) {
                uint32_t t[4];
                ldsm4(t, sb + SWZ(boff[p] + k16 * 32));
                bF[2 * p][0] = t[0];
                bF[2 * p][1] = t[2];
                bF[2 * p + 1][0] = t[1];
                bF[2 * p + 1][1] = t[3];
            }
#pragma unroll
            for (int mt = 0; mt < 4; mt++)
#pragma unroll
                for (int nt = 0; nt < 4; nt++)
                    mma16816(acc[mt][nt], aF[mt], bF[nt]);
        }
    }

    const int g = lane >> 2, t4 = lane & 3;
#pragma unroll
    for (int mt = 0; mt < 4; mt++) {
        const int r0 = by * BM + wm * 64 + mt * 16 + g;
        size_t rowbase, rowbase8;
        if (MODE == 0) {
            rowbase = (size_t)r0 * NH;
            rowbase8 = (size_t)(r0 + 8) * NH;
        } else {
            rowbase = (size_t)((r0 & 63) * 64 + (r0 >> 6)) * NH;
            rowbase8 = (size_t)(((r0 + 8) & 63) * 64 + ((r0 + 8) >> 6)) * NH;
        }
#pragma unroll
        for (int nt = 0; nt < 4; nt++) {
            const int c0 = bx * BN + wn * 32 + nt * 8 + t4 * 2;
            float2 bb2 = *(const float2*)&bias[c0];
            float v0 = acc[mt][nt][0] + bb2.x, v1 = acc[mt][nt][1] + bb2.y;
            float v2 = acc[mt][nt][2] + bb2.x, v3 = acc[mt][nt][3] + bb2.y;
            if (MODE == 1) {
                v0 = fminf(fmaxf(v0, 0.f), 1.f);
                v1 = fminf(fmaxf(v1, 0.f), 1.f);
                v2 = fminf(fmaxf(v2, 0.f), 1.f);
                v3 = fminf(fmaxf(v3, 0.f), 1.f);
            }
            float2 w0 = {v0, v1}, w1 = {v2, v3};
            *(float2*)&C[rowbase + c0] = w0;
            *(float2*)&C[rowbase8 + c0] = w1;
        }
    }
}

__global__ void __launch_bounds__(256, 2) gemm0_k() {
    extern __shared__ char dsm[];
    gemm_body<0>(dsm, blockIdx.x, g_Ax, g_B0, g_bpre, g_pre);
}
__global__ void __launch_bounds__(256, 2) gemm1_k(const float* __restrict__ b_out,
                                                  float* __restrict__ out) {
    extern __shared__ char dsm[];
    gemm_body<1>(dsm, blockIdx.x, g_Ah, g_B1, b_out, out);
}

// ---------------- recurrence: one block/batch, 512 threads, h in regs --------
// smem floats: skey_h fp16[20][2048] (20480 fl) | sread_h fp16[20][2048]
// (20480 fl) | spart[20][512] | sbank 2560 | spre 2048 | sbn 512 |
// ssim 128 | sprob 128 | sk 24 | sr 24
#define RC_KEYH 0
#define RC_READH 20480
#define RC_PART 40960
#define RC_BANK (RC_PART + MW * 512)  // 51200
#define RC_PRE (RC_BANK + MN * MW)    // 53760
#define RC_BN (RC_PRE + NH)           // 55808
#define RC_SIM (RC_BN + 512)          // 56320
#define RC_PROB (RC_SIM + MN)         // 56448
#define RC_K (RC_PROB + MN)           // 56576
#define RC_R (RC_K + 24)              // 56600
#define RECUR_SMEM ((RC_R + 24) * 4)  // 226,496 B

__global__ void __launch_bounds__(512, 1)
recur_k(const float* __restrict__ h0, const float* __restrict__ b_key,
        const float* __restrict__ W_read, const float* __restrict__ memory,
        const float* __restrict__ W_key) {
    extern __shared__ float rs[];
    __half* skey = (__half*)(rs + RC_KEYH);   // [j][r] j-major
    __half* sread = (__half*)(rs + RC_READH); // [m][c] m-major
    float* spart = rs + RC_PART;
    float* sbank = rs + RC_BANK;
    float* spre = rs + RC_PRE;
    float* sbn = rs + RC_BN;
    float* ssim = rs + RC_SIM;
    float* sprob = rs + RC_PROB;
    float* sk = rs + RC_K;
    float* sr = rs + RC_R;
    const uint32_t sbank_u = s2u(sbank);
    const uint32_t spre_u = s2u(spre);

    const int b = blockIdx.x;
    const int tid = threadIdx.x;
    const int lane = tid & 31, warp = tid >> 5;

    // hidden state: thread owns rows 4*tid .. 4*tid+3 (registers)
    float4 v = ((const float4*)(h0 + (size_t)b * NH))[tid];

    // W_key j-major fp16; W_read m-major fp16
    for (int i = tid; i < MW * NH; i += 512) {
        int j = i >> 11, r = i & (NH - 1);
        skey[i] = __float2half_rn(W_key[(size_t)r * MW + j]);
        sread[i] = __float2half_rn(W_read[i]);  // i = m*2048 + c exactly
    }
    // bank norms (all 4 banks)
    for (int i = tid; i < MBK * MN; i += 512) {
        float s = 0.f;
        const float* row = memory + (size_t)i * MW;
#pragma unroll
        for (int m = 0; m < MW; m++) s += row[m] * row[m];
        sbn[i] = sqrtf(s);
    }
    __syncthreads();

    for (int t = 0; t < T_SZ; t++) {
        const int bkx = t & (MBK - 1);
        const float* bank = memory + (size_t)bkx * MN * MW;
        // group1: bank tile (10240 B)
        for (int i = tid; i < MN * MW / 4; i += 512)
            cpa16(sbank_u + i * 16, bank + i * 4);
        CP_COMMIT;
        // group2: this step's pre row (own 16B chunk)
        cpa16(spre_u + tid * 16, g_pre + (size_t)(t * 64 + b) * NH + tid * 4);
        CP_COMMIT;

        // ---- k partials: 20 x LDS.64 (fp16 pairs) on own rows ----
#pragma unroll
        for (int j = 0; j < MW; j++) {
            const __half2* kp = (const __half2*)(skey + j * NH + 4 * tid);
            float2 w0 = __half22float2(kp[0]);
            float2 w1 = __half22float2(kp[1]);
            spart[j * 512 + tid] =
                v.x * w0.x + v.y * w0.y + v.z * w1.x + v.w * w1.y;
        }
        __syncthreads();  // A: partials ready

        // ---- stage2: warp w reduces j=w; warps 0..3 also j=16+w ----
        {
            int jj = warp;
#pragma unroll
            for (int round = 0; round < 2; round++) {
                if (jj < MW) {
                    const float* pp = spart + jj * 512 + lane;
                    float s = 0.f;
#pragma unroll
                    for (int i = 0; i < 16; i++) s += pp[32 * i];
#pragma unroll
                    for (int o = 16; o > 0; o >>= 1)
                        s += __shfl_xor_sync(0xffffffffu, s, o);
                    if (lane == 0) sk[jj] = s + b_key[jj];
                }
                jj = warp + 16;
            }
        }
        cp_wait1();       // bank tile arrived (spre may still be in flight)
        __syncthreads();  // B: sk + sbank visible to all

        // ---- sim: warps 0..7, 16 rows each, from sbank ----
        if (warp < 8) {
            float kv = (lane < MW) ? sk[lane] : 0.f;
            float sq = kv * kv;
#pragma unroll
            for (int o = 16; o > 0; o >>= 1)
                sq += __shfl_xor_sync(0xffffffffu, sq, o);
            const float kn = sqrtf(sq);
            if (lane < 16) {
                const int row = warp * 16 + lane;
                const float4* bn = (const float4*)(sbank + row * MW);
                float d = 0.f;
#pragma unroll
                for (int j4 = 0; j4 < 5; j4++) {
                    float4 w = bn[j4];
                    d += sk[j4 * 4 + 0] * w.x + sk[j4 * 4 + 1] * w.y +
                         sk[j4 * 4 + 2] * w.z + sk[j4 * 4 + 3] * w.w;
                }
                ssim[row] = d / (kn * sbn[bkx * MN + row] + 1e-8f);
            }
        }
        __syncthreads();  // C: sim ready

        // ---- softmax over 128 (warp 0) ----
        if (warp == 0) {
            float pv[4];
#pragma unroll
            for (int q = 0; q < 4; q++) pv[q] = ssim[q * 32 + lane];
            float mx = fmaxf(fmaxf(pv[0], pv[1]), fmaxf(pv[2], pv[3]));
#pragma unroll
            for (int o = 16; o > 0; o >>= 1)
                mx = fmaxf(mx, __shfl_xor_sync(0xffffffffu, mx, o));
            float e[4], s = 0.f;
#pragma unroll
            for (int q = 0; q < 4; q++) {
                e[q] = expf(pv[q] - mx);
                s += e[q];
            }
#pragma unroll
            for (int o = 16; o > 0; o >>= 1)
                s += __shfl_xor_sync(0xffffffffu, s, o);
            const float inv = 1.f / s;
#pragma unroll
            for (int q = 0; q < 4; q++) sprob[q * 32 + lane] = e[q] * inv;
        }
        __syncthreads();  // D: prob ready

        // ---- r: warps 0..3, each 5 outputs, from sbank ----
        if (warp < 4) {
#pragma unroll
            for (int q = 0; q < 5; q++) {
                const int j = warp * 5 + q;
                float a = 0.f;
#pragma unroll
                for (int m = 0; m < 4; m++) {
                    const int n = lane + 32 * m;
                    a += sprob[n] * sbank[n * MW + j];
                }
#pragma unroll
                for (int o = 16; o > 0; o >>= 1)
                    a += __shfl_xor_sync(0xffffffffu, a, o);
                if (lane == 0) sr[j] = a;
            }
        }
        __syncthreads();  // E: r ready

        // ---- epilogue: h_new (regs) = relu(pre + r @ W_read_smem) ----
        {
            cp_wait0();  // own spre chunk ready (self-visible)
            float4 p = ((const float4*)spre)[tid];
#pragma unroll
            for (int m = 0; m < MW; m++) {
                const float rm = sr[m];
                const __half2* rp = (const __half2*)(sread + m * NH + 4 * tid);
                float2 w0 = __half22float2(rp[0]);
                float2 w1 = __half22float2(rp[1]);
                p.x += rm * w0.x; p.y += rm * w0.y;
                p.z += rm * w1.x; p.w += rm * w1.y;
            }
            v.x = fmaxf(p.x, 0.f); v.y = fmaxf(p.y, 0.f);
            v.z = fmaxf(p.z, 0.f); v.w = fmaxf(p.w, 0.f);

            const size_t rowb = (size_t)(t * 64 + b) * KW;
            __half hx = __float2half_rn(v.x), hy = __float2half_rn(v.y);
            __half hz = __float2half_rn(v.z), hw = __float2half_rn(v.w);
            __half2* ph = (__half2*)(g_Ah + rowb + 4 * tid);
            ph[0] = __halves2half2(hx, hy);
            ph[1] = __halves2half2(hz, hw);
            __half2* pl = (__half2*)(g_Ah + rowb + 2048 + 4 * tid);
            pl[0] = __halves2half2(
                __float2half_rn(v.x - __half2float(hx)),
                __float2half_rn(v.y - __half2float(hy)));
            pl[1] = __halves2half2(
                __float2half_rn(v.z - __half2float(hz)),
                __float2half_rn(v.w - __half2float(hw)));
        }
        // no trailing barrier: every next-step shared write happens after a
        // subsequent barrier (A..E).
    }
}

// ---------------- host -------------------------------------------------------
extern "C" void kernel_launch(void* const* d_in, const int* in_sizes, int n_in,
                              void* d_out, int out_size) {
    const float* x      = (const float*)d_in[0];
    const float* h0     = (const float*)d_in[1];
    const float* W_in   = (const float*)d_in[2];
    const float* b_in   = (const float*)d_in[3];
    const float* W_read = (const float*)d_in[4];
    const float* b_read = (const float*)d_in[5];
    const float* W_out  = (const float*)d_in[6];
    const float* b_out  = (const float*)d_in[7];
    const float* W_key  = (const float*)d_in[8];
    const float* b_key  = (const float*)d_in[9];
    const float* memory = (const float*)d_in[10];
    float* out = (float*)d_out;

    cudaFuncSetAttribute(gemm0_k, cudaFuncAttributeMaxDynamicSharedMemorySize,
                         GEMM_SMEM);
    cudaFuncSetAttribute(gemm1_k, cudaFuncAttributeMaxDynamicSharedMemorySize,
                         GEMM_SMEM);
    cudaFuncSetAttribute(recur_k, cudaFuncAttributeMaxDynamicSharedMemorySize,
                         RECUR_SMEM);

    conv_x<<<(M_ROWS * NI / 4 + 255) / 256, 256>>>((const float4*)x);
    trans_split<<<dim3(64, 64, 2), dim3(32, 8)>>>(W_in, W_out);
    bias_comb<<<4, 512>>>(b_in, b_read);

    gemm0_k<<<512, 256, GEMM_SMEM>>>();
    recur_k<<<B_SZ, 512, RECUR_SMEM>>>(h0, b_key, W_read, memory, W_key);
    gemm1_k<<<512, 256, GEMM_SMEM>>>(b_out, out);
}

// round 17
// speedup vs baseline: 2.7624x; 1.4476x over previous
#include <cuda_runtime.h>
#include <cuda_fp16.h>
#include <math.h>
#include <stdint.h>

#define B_SZ 64
#define T_SZ 64
#define NI 2048
#define NH 2048
#define MBK 4
#define MN 128
#define MW 20
#define M_ROWS 4096
#define KW 2048   // A width (single fp16)
#define KB 2048   // B width (single fp16)
#define KXT 2048  // logical K of the GEMM

// ---------------- device scratch (t-major rows: r = t*64 + b) ----------------
__device__ float g_pre[(size_t)M_ROWS * NH];
__device__ float g_bpre[NH];
__device__ __half g_Ax[(size_t)M_ROWS * KW];   // x fp16
__device__ __half g_Ah[(size_t)M_ROWS * KW];   // H fp16
__device__ __half g_B0[(size_t)NH * KB];       // W_in^T  fp16
__device__ __half g_B1[(size_t)NH * KB];       // W_out^T fp16

// ---------------- helpers ----------------------------------------------------
__device__ __forceinline__ uint32_t s2u(const void* p) {
    uint32_t r;
    asm("{ .reg .u64 t; cvta.to.shared.u64 t, %1; cvt.u32.u64 %0, t; }"
        : "=r"(r) : "l"(p));
    return r;
}
#define SWZ(x) ((x) ^ (((x) >> 3) & 0x70))
__device__ __forceinline__ void cpa16(uint32_t s, const void* g) {
    asm volatile("cp.async.cg.shared.global [%0], [%1], 16;" :: "r"(s), "l"(g)
                 : "memory");
}
#define CP_COMMIT asm volatile("cp.async.commit_group;" ::: "memory")
__device__ __forceinline__ void cp_wait1() {
    asm volatile("cp.async.wait_group 1;" ::: "memory");
}
__device__ __forceinline__ void cp_wait0() {
    asm volatile("cp.async.wait_group 0;" ::: "memory");
}
__device__ __forceinline__ void ldsm4(uint32_t* r, uint32_t a) {
    asm volatile("ldmatrix.sync.aligned.m8n8.x4.shared.b16 {%0,%1,%2,%3}, [%4];"
                 : "=r"(r[0]), "=r"(r[1]), "=r"(r[2]), "=r"(r[3]) : "r"(a));
}
__device__ __forceinline__ void mma16816(float* c, const uint32_t* a,
                                         const uint32_t* b) {
    asm volatile(
        "mma.sync.aligned.m16n8k16.row.col.f32.f16.f16.f32 "
        "{%0,%1,%2,%3}, {%4,%5,%6,%7}, {%8,%9}, {%0,%1,%2,%3};"
        : "+f"(c[0]), "+f"(c[1]), "+f"(c[2]), "+f"(c[3])
        : "r"(a[0]), "r"(a[1]), "r"(a[2]), "r"(a[3]), "r"(b[0]), "r"(b[1]));
}

// ---------------- small prep kernels -----------------------------------------
__global__ void conv_x(const float4* __restrict__ x4) {
    int i = blockIdx.x * 256 + threadIdx.x;
    if (i >= M_ROWS * NI / 4) return;
    int row = i >> 9, c4 = i & 511;          // input row = b*64 + t
    int b = row >> 6, t = row & 63;
    int orow = t * 64 + b;                   // t-major
    float4 v = x4[i];
    __half2* p = (__half2*)(g_Ax + (size_t)orow * KW);
    p[2 * c4] = __halves2half2(__float2half_rn(v.x), __float2half_rn(v.y));
    p[2 * c4 + 1] = __halves2half2(__float2half_rn(v.z), __float2half_rn(v.w));
}

// z=0: W_in -> g_B0, z=1: W_out -> g_B1
__global__ void trans_split(const float* __restrict__ W0,
                            const float* __restrict__ W1) {
    __shared__ float s[32][33];
    const float* W = blockIdx.z ? W1 : W0;
    __half* T = blockIdx.z ? g_B1 : g_B0;
    int n0 = blockIdx.x * 32, k0 = blockIdx.y * 32;
    int tx = threadIdx.x, ty = threadIdx.y;
#pragma unroll
    for (int i = 0; i < 32; i += 8)
        s[ty + i][tx] = W[(size_t)(k0 + ty + i) * NH + n0 + tx];
    __syncthreads();
#pragma unroll
    for (int i = 0; i < 32; i += 8) {
        T[(size_t)(n0 + ty + i) * KB + k0 + tx] = __float2half_rn(s[tx][ty + i]);
    }
}

__global__ void bias_comb(const float* __restrict__ a,
                          const float* __restrict__ b) {
    int i = blockIdx.x * 512 + threadIdx.x;
    if (i < NH) g_bpre[i] = a[i] + b[i];
}

// ---------------- GEMM ------------------------------------------------------
#define BM 128
#define BN 128
#define BK 64
#define STG 3
#define STAGE_B 32768
#define NT (KXT / BK)  // 32
#define GEMM_SMEM (STG * STAGE_B + 1024)  // 99328

template <int MODE>  // 0: C=g_pre (t-major) | 1: C=out remap+clamp
__device__ void gemm_body(char* dsm, int cta,
                          const __half* __restrict__ Ag,
                          const __half* __restrict__ Bg,
                          const float* __restrict__ bias,
                          float* __restrict__ C) {
    const int by = cta >> 4, bx = cta & 15;
    const int tid = threadIdx.x, lane = tid & 31, wid = tid >> 5;
    const int wm = wid & 1, wn = wid >> 1;

    uint32_t base = (s2u(dsm) + 1023u) & ~1023u;
    const __half* Abase = Ag + (size_t)(by * BM + (tid >> 3)) * KW +
                          (tid & 7) * 8;
    const __half* Bbase = Bg + (size_t)(bx * BN + (tid >> 3)) * KB +
                          (tid & 7) * 8;

    float acc[4][4][4];
#pragma unroll
    for (int m = 0; m < 4; m++)
#pragma unroll
        for (int n = 0; n < 4; n++)
#pragma unroll
            for (int q = 0; q < 4; q++) acc[m][n][q] = 0.f;

    uint32_t stoff[4];
#pragma unroll
    for (int u = 0; u < 4; u++) {
        int unit = tid + 256 * u;
        stoff[u] = SWZ((uint32_t)((unit >> 3) * 128 + (unit & 7) * 16));
    }

    auto load_stage = [&](int s, int ks) {
        int kk = ks * 64;
        uint32_t sb = base + s * STAGE_B;
#pragma unroll
        for (int u = 0; u < 4; u++)
            cpa16(sb + stoff[u], Abase + (size_t)(32 * u) * KW + kk);
#pragma unroll
        for (int u = 0; u < 4; u++)
            cpa16(sb + 16384 + stoff[u], Bbase + (size_t)(32 * u) * KB + kk);
    };

    load_stage(0, 0);
    CP_COMMIT;
    load_stage(1, 1);
    CP_COMMIT;

    uint32_t aoff[4], boff[2];
#pragma unroll
    for (int mt = 0; mt < 4; mt++)
        aoff[mt] = (uint32_t)((wm * 64 + mt * 16 + (lane & 15)) * 128 +
                              (lane >> 4) * 16);
#pragma unroll
    for (int p = 0; p < 2; p++)
        boff[p] = (uint32_t)((wn * 32 + p * 16 + (lane & 15)) * 128 +
                             (lane >> 4) * 16);

    for (int ks = 0; ks < NT; ks++) {
        if (ks < NT - 1) cp_wait1();
        else cp_wait0();
        __syncthreads();
        if (ks + 2 < NT) {
            load_stage((ks + 2) % STG, ks + 2);
            CP_COMMIT;
        }
        const uint32_t sa = base + (ks % STG) * STAGE_B;
        const uint32_t sb = sa + 16384;
#pragma unroll
        for (int k16 = 0; k16 < 4; k16++) {
            uint32_t aF[4][4], bF[4][2];
#pragma unroll
            for (int mt = 0; mt < 4; mt++)
                ldsm4(aF[mt], sa + SWZ(aoff[mt] + k16 * 32));
#pragma unroll
            for (int p = 0; p < 2; p++) {
                uint32_t t[4];
                ldsm4(t, sb + SWZ(boff[p] + k16 * 32));
                bF[2 * p][0] = t[0];
                bF[2 * p][1] = t[2];
                bF[2 * p + 1][0] = t[1];
                bF[2 * p + 1][1] = t[3];
            }
#pragma unroll
            for (int mt = 0; mt < 4; mt++)
#pragma unroll
                for (int nt = 0; nt < 4; nt++)
                    mma16816(acc[mt][nt], aF[mt], bF[nt]);
        }
    }

    const int g = lane >> 2, t4 = lane & 3;
#pragma unroll
    for (int mt = 0; mt < 4; mt++) {
        const int r0 = by * BM + wm * 64 + mt * 16 + g;
        size_t rowbase, rowbase8;
        if (MODE == 0) {
            rowbase = (size_t)r0 * NH;
            rowbase8 = (size_t)(r0 + 8) * NH;
        } else {
            rowbase = (size_t)((r0 & 63) * 64 + (r0 >> 6)) * NH;
            rowbase8 = (size_t)(((r0 + 8) & 63) * 64 + ((r0 + 8) >> 6)) * NH;
        }
#pragma unroll
        for (int nt = 0; nt < 4; nt++) {
            const int c0 = bx * BN + wn * 32 + nt * 8 + t4 * 2;
            float2 bb2 = *(const float2*)&bias[c0];
            float v0 = acc[mt][nt][0] + bb2.x, v1 = acc[mt][nt][1] + bb2.y;
            float v2 = acc[mt][nt][2] + bb2.x, v3 = acc[mt][nt][3] + bb2.y;
            if (MODE == 1) {
                v0 = fminf(fmaxf(v0, 0.f), 1.f);
                v1 = fminf(fmaxf(v1, 0.f), 1.f);
                v2 = fminf(fmaxf(v2, 0.f), 1.f);
                v3 = fminf(fmaxf(v3, 0.f), 1.f);
            }
            float2 w0 = {v0, v1}, w1 = {v2, v3};
            *(float2*)&C[rowbase + c0] = w0;
            *(float2*)&C[rowbase8 + c0] = w1;
        }
    }
}

__global__ void __launch_bounds__(256, 2) gemm0_k() {
    extern __shared__ char dsm[];
    gemm_body<0>(dsm, blockIdx.x, g_Ax, g_B0, g_bpre, g_pre);
}
__global__ void __launch_bounds__(256, 2) gemm1_k(const float* __restrict__ b_out,
                                                  float* __restrict__ out) {
    extern __shared__ char dsm[];
    gemm_body<1>(dsm, blockIdx.x, g_Ah, g_B1, b_out, out);
}

// ---------------- recurrence: one block/batch, 512 threads, h in regs --------
// smem floats: skey_h fp16[20][2048] (20480 fl) | sread_h fp16[20][2048]
// (20480 fl) | spart[20][512] | sbank 2560 | spre 2048 | sbn 512 |
// ssim 128 | sprob 128 | sk 24 | sr 24
#define RC_KEYH 0
#define RC_READH 20480
#define RC_PART 40960
#define RC_BANK (RC_PART + MW * 512)  // 51200
#define RC_PRE (RC_BANK + MN * MW)    // 53760
#define RC_BN (RC_PRE + NH)           // 55808
#define RC_SIM (RC_BN + 512)          // 56320
#define RC_PROB (RC_SIM + MN)         // 56448
#define RC_K (RC_PROB + MN)           // 56576
#define RC_R (RC_K + 24)              // 56600
#define RECUR_SMEM ((RC_R + 24) * 4)  // 226,496 B

__global__ void __launch_bounds__(512, 1)
recur_k(const float* __restrict__ h0, const float* __restrict__ b_key,
        const float* __restrict__ W_read, const float* __restrict__ memory,
        const float* __restrict__ W_key) {
    extern __shared__ float rs[];
    __half* skey = (__half*)(rs + RC_KEYH);   // [j][r] j-major
    __half* sread = (__half*)(rs + RC_READH); // [m][c] m-major
    float* spart = rs + RC_PART;
    float* sbank = rs + RC_BANK;
    float* spre = rs + RC_PRE;
    float* sbn = rs + RC_BN;
    float* ssim = rs + RC_SIM;
    float* sprob = rs + RC_PROB;
    float* sk = rs + RC_K;
    float* sr = rs + RC_R;
    const uint32_t sbank_u = s2u(sbank);
    const uint32_t spre_u = s2u(spre);

    const int b = blockIdx.x;
    const int tid = threadIdx.x;
    const int lane = tid & 31, warp = tid >> 5;

    // hidden state: thread owns rows 4*tid .. 4*tid+3 (registers)
    float4 v = ((const float4*)(h0 + (size_t)b * NH))[tid];

    // W_key j-major fp16; W_read m-major fp16
    for (int i = tid; i < MW * NH; i += 512) {
        int j = i >> 11, r = i & (NH - 1);
        skey[i] = __float2half_rn(W_key[(size_t)r * MW + j]);
        sread[i] = __float2half_rn(W_read[i]);  // i = m*2048 + c exactly
    }
    // bank norms (all 4 banks)
    for (int i = tid; i < MBK * MN; i += 512) {
        float s = 0.f;
        const float* row = memory + (size_t)i * MW;
#pragma unroll
        for (int m = 0; m < MW; m++) s += row[m] * row[m];
        sbn[i] = sqrtf(s);
    }
    __syncthreads();

    for (int t = 0; t < T_SZ; t++) {
        const int bkx = t & (MBK - 1);
        const float* bank = memory + (size_t)bkx * MN * MW;
        // group1: bank tile (10240 B)
        for (int i = tid; i < MN * MW / 4; i += 512)
            cpa16(sbank_u + i * 16, bank + i * 4);
        CP_COMMIT;
        // group2: this step's pre row (own 16B chunk)
        cpa16(spre_u + tid * 16, g_pre + (size_t)(t * 64 + b) * NH + tid * 4);
        CP_COMMIT;

        // ---- k partials: 20 x LDS.64 (fp16 pairs) on own rows ----
#pragma unroll
        for (int j = 0; j < MW; j++) {
            const __half2* kp = (const __half2*)(skey + j * NH + 4 * tid);
            float2 w0 = __half22float2(kp[0]);
            float2 w1 = __half22float2(kp[1]);
            spart[j * 512 + tid] =
                v.x * w0.x + v.y * w0.y + v.z * w1.x + v.w * w1.y;
        }
        __syncthreads();  // A: partials ready

        // ---- stage2: warp w reduces j=w; warps 0..3 also j=16+w ----
        {
            int jj = warp;
#pragma unroll
            for (int round = 0; round < 2; round++) {
                if (jj < MW) {
                    const float* pp = spart + jj * 512 + lane;
                    float s = 0.f;
#pragma unroll
                    for (int i = 0; i < 16; i++) s += pp[32 * i];
#pragma unroll
                    for (int o = 16; o > 0; o >>= 1)
                        s += __shfl_xor_sync(0xffffffffu, s, o);
                    if (lane == 0) sk[jj] = s + b_key[jj];
                }
                jj = warp + 16;
            }
        }
        cp_wait1();       // bank tile arrived (spre may still be in flight)
        __syncthreads();  // B: sk + sbank visible to all

        // ---- sim: warps 0..7, 16 rows each, from sbank ----
        if (warp < 8) {
            float kv = (lane < MW) ? sk[lane] : 0.f;
            float sq = kv * kv;
#pragma unroll
            for (int o = 16; o > 0; o >>= 1)
                sq += __shfl_xor_sync(0xffffffffu, sq, o);
            const float kn = sqrtf(sq);
            if (lane < 16) {
                const int row = warp * 16 + lane;
                const float4* bn = (const float4*)(sbank + row * MW);
                float d = 0.f;
#pragma unroll
                for (int j4 = 0; j4 < 5; j4++) {
                    float4 w = bn[j4];
                    d += sk[j4 * 4 + 0] * w.x + sk[j4 * 4 + 1] * w.y +
                         sk[j4 * 4 + 2] * w.z + sk[j4 * 4 + 3] * w.w;
                }
                ssim[row] = d / (kn * sbn[bkx * MN + row] + 1e-8f);
            }
        }
        __syncthreads();  // C: sim ready

        // ---- softmax over 128 (warp 0) ----
        if (warp == 0) {
            float pv[4];
#pragma unroll
            for (int q = 0; q < 4; q++) pv[q] = ssim[q * 32 + lane];
            float mx = fmaxf(fmaxf(pv[0], pv[1]), fmaxf(pv[2], pv[3]));
#pragma unroll
            for (int o = 16; o > 0; o >>= 1)
                mx = fmaxf(mx, __shfl_xor_sync(0xffffffffu, mx, o));
            float e[4], s = 0.f;
#pragma unroll
            for (int q = 0; q < 4; q++) {
                e[q] = expf(pv[q] - mx);
                s += e[q];
            }
#pragma unroll
            for (int o = 16; o > 0; o >>= 1)
                s += __shfl_xor_sync(0xffffffffu, s, o);
            const float inv = 1.f / s;
#pragma unroll
            for (int q = 0; q < 4; q++) sprob[q * 32 + lane] = e[q] * inv;
        }
        __syncthreads();  // D: prob ready

        // ---- r: warps 0..3, each 5 outputs, from sbank ----
        if (warp < 4) {
#pragma unroll
            for (int q = 0; q < 5; q++) {
                const int j = warp * 5 + q;
                float a = 0.f;
#pragma unroll
                for (int m = 0; m < 4; m++) {
                    const int n = lane + 32 * m;
                    a += sprob[n] * sbank[n * MW + j];
                }
#pragma unroll
                for (int o = 16; o > 0; o >>= 1)
                    a += __shfl_xor_sync(0xffffffffu, a, o);
                if (lane == 0) sr[j] = a;
            }
        }
        __syncthreads();  // E: r ready

        // ---- epilogue: h_new (regs) = relu(pre + r @ W_read_smem) ----
        {
            cp_wait0();  // own spre chunk ready (self-visible)
            float4 p = ((const float4*)spre)[tid];
#pragma unroll
            for (int m = 0; m < MW; m++) {
                const float rm = sr[m];
                const __half2* rp = (const __half2*)(sread + m * NH + 4 * tid);
                float2 w0 = __half22float2(rp[0]);
                float2 w1 = __half22float2(rp[1]);
                p.x += rm * w0.x; p.y += rm * w0.y;
                p.z += rm * w1.x; p.w += rm * w1.y;
            }
            v.x = fmaxf(p.x, 0.f); v.y = fmaxf(p.y, 0.f);
            v.z = fmaxf(p.z, 0.f); v.w = fmaxf(p.w, 0.f);

            const size_t rowb = (size_t)(t * 64 + b) * KW;
            __half2* ph = (__half2*)(g_Ah + rowb + 4 * tid);
            ph[0] = __halves2half2(__float2half_rn(v.x), __float2half_rn(v.y));
            ph[1] = __halves2half2(__float2half_rn(v.z), __float2half_rn(v.w));
        }
        // no trailing barrier: every next-step shared write happens after a
        // subsequent barrier (A..E).
    }
}

// ---------------- host -------------------------------------------------------
extern "C" void kernel_launch(void* const* d_in, const int* in_sizes, int n_in,
                              void* d_out, int out_size) {
    const float* x      = (const float*)d_in[0];
    const float* h0     = (const float*)d_in[1];
    const float* W_in   = (const float*)d_in[2];
    const float* b_in   = (const float*)d_in[3];
    const float* W_read = (const float*)d_in[4];
    const float* b_read = (const float*)d_in[5];
    const float* W_out  = (const float*)d_in[6];
    const float* b_out  = (const float*)d_in[7];
    const float* W_key  = (const float*)d_in[8];
    const float* b_key  = (const float*)d_in[9];
    const float* memory = (const float*)d_in[10];
    float* out = (float*)d_out;

    cudaFuncSetAttribute(gemm0_k, cudaFuncAttributeMaxDynamicSharedMemorySize,
                         GEMM_SMEM);
    cudaFuncSetAttribute(gemm1_k, cudaFuncAttributeMaxDynamicSharedMemorySize,
                         GEMM_SMEM);
    cudaFuncSetAttribute(recur_k, cudaFuncAttributeMaxDynamicSharedMemorySize,
                         RECUR_SMEM);

    conv_x<<<(M_ROWS * NI / 4 + 255) / 256, 256>>>((const float4*)x);
    trans_split<<<dim3(64, 64, 2), dim3(32, 8)>>>(W_in, W_out);
    bias_comb<<<4, 512>>>(b_in, b_read);

    gemm0_k<<<512, 256, GEMM_SMEM>>>();
    recur_k<<<B_SZ, 512, RECUR_SMEM>>>(h0, b_key, W_read, memory, W_key);
    gemm1_k<<<512, 256, GEMM_SMEM>>>(b_out, out);
}